// round 3
// baseline (speedup 1.0000x reference)
#include <cuda_runtime.h>
#include <cstdint>

#define Bn   64
#define Nn   207
#define Tn   48
#define Fin  6
#define Hd   64
#define NSEQ (Bn * Nn)        // 13248

// scratch: GCN output / LSTM input, [seq][t][Hd]
__device__ float g_h2[(size_t)NSEQ * Tn * Hd];   // 162.8 MB

#define PACK2(d, s)    asm("mov.b64 %0, {%1, %1};" : "=l"(d) : "f"(s))
#define UNPK2(a, b, v) asm("mov.b64 {%0, %1}, %2;" : "=f"(a), "=f"(b) : "l"(v))
#define FMA2(acc, a, b) asm("fma.rn.f32x2 %0, %1, %2, %0;" : "+l"(acc) : "l"(a), "l"(b))

__device__ __forceinline__ float tanhm(float x) {
    float r; asm("tanh.approx.f32 %0, %1;" : "=f"(r) : "f"(x)); return r;
}
// sigmoid(x + b) with bh = 0.5*b precomputed
__device__ __forceinline__ float sigm2(float x, float bh) {
    return fmaf(tanhm(fmaf(x, 0.5f, bh)), 0.5f, 0.5f);
}

// =====================================================================
// Kernel 1: fused 2-layer GCN.  grid (Tn, Bn), 256 threads.
// A_hat[m][n] = (1 + (m==n)) / 208
// =====================================================================
#define NS 216   // padded row stride of bufT (16B-aligned)

__global__ void __launch_bounds__(256, 2) gcn_kernel(
    const float* __restrict__ x,  const float* __restrict__ W1,
    const float* __restrict__ b1, const float* __restrict__ W2,
    const float* __restrict__ b2)
{
    extern __shared__ float sm[];
    float* W1s  = sm;               // 384
    float* W2s  = W1s + 384;        // 4096
    float* b1s  = W2s + 4096;       // 64
    float* b2s  = b1s + 64;         // 64
    float* S1   = b2s + 64;         // 64
    float* SH   = S1 + 64;          // 64
    float* S2   = SH + 64;          // 64
    float* xsum = S2 + 64;          // 8
    float* part = xsum + 8;         // 256
    float* xs   = part + 256;       // 1248 (uses 1242)
    float* bufT = xs + 1248;        // 64 * NS  (h1 transposed [k][n])

    const int t = blockIdx.x, b = blockIdx.y;
    const int tid = threadIdx.x;
    const float inv = 1.0f / 208.0f;

    for (int i = tid; i < 384;  i += 256) W1s[i] = W1[i];
    for (int i = tid; i < 4096; i += 256) W2s[i] = W2[i];
    if (tid < 64) { b1s[tid] = b1[tid]; b2s[tid] = b2[tid]; }
    {
        const float* xb = x + (size_t)b * (Nn * Tn * Fin) + t * Fin;
        for (int i = tid; i < Nn * Fin; i += 256) {
            int n = i / 6, f = i - n * 6;
            xs[i] = xb[n * (Tn * Fin) + f];
        }
    }
    // zero padded tail of bufT rows (n = 207..215)
    for (int i = tid; i < 64 * 9; i += 256) {
        int j = i / 9, p = i - j * 9;
        bufT[j * NS + 207 + p] = 0.f;
    }
    __syncthreads();

    // xsum[f] = sum_n x[n][f]
    if (tid < 48) {
        int f = tid % 6, q = tid / 6;
        float s = 0.f;
        for (int n = q; n < Nn; n += 8) s += xs[n * 6 + f];
        part[tid] = s;
    }
    __syncthreads();
    if (tid < 6) {
        float s = 0.f;
        #pragma unroll
        for (int q = 0; q < 8; ++q) s += part[q * 6 + tid];
        xsum[tid] = s;
    }
    __syncthreads();
    // S1 = xsum @ W1  (colsum of z1)
    if (tid < 64) {
        float s = 0.f;
        #pragma unroll
        for (int f = 0; f < 6; ++f) s += xsum[f] * W1s[f * 64 + tid];
        S1[tid] = s;
    }
    __syncthreads();

    // h1 = relu((z1 + S1)/208 + b1), stored transposed bufT[j][n]
    {
        int j = tid >> 2, q = tid & 3;
        float w0 = W1s[j], w1 = W1s[64 + j], w2 = W1s[128 + j];
        float w3 = W1s[192 + j], w4 = W1s[256 + j], w5 = W1s[320 + j];
        float cj = fmaf(S1[j], inv, b1s[j]);
        float* row = bufT + j * NS;
        for (int n = q; n < Nn; n += 4) {
            const float* xr = xs + n * 6;
            float v = xr[0] * w0 + xr[1] * w1 + xr[2] * w2
                    + xr[3] * w3 + xr[4] * w4 + xr[5] * w5;
            row[n] = fmaxf(fmaf(v, inv, cj), 0.f);
        }
    }
    __syncthreads();

    // SH[j] = sum_n h1[j][n]
    {
        int j = tid >> 2, q = tid & 3;
        const float* row = bufT + j * NS;
        float s = 0.f;
        for (int n = q; n < Nn; n += 4) s += row[n];
        part[q * 64 + j] = s;
    }
    __syncthreads();
    if (tid < 64) SH[tid] = part[tid] + part[64 + tid] + part[128 + tid] + part[192 + tid];
    __syncthreads();
    // S2 = SH @ W2  (colsum of z2)
    if (tid < 64) {
        float s = 0.f;
        #pragma unroll 8
        for (int k = 0; k < 64; ++k) s += SH[k] * W2s[k * 64 + tid];
        S2[tid] = s;
    }
    __syncthreads();

    // z2 = h1 @ W2 ; h2 = relu((z2 + S2)/208 + b2) -> global
    // acc packs n-pairs; lane owns units j=lane and j=lane+32.
    {
        const int w = tid >> 5, lane = tid & 31;
        const float a0 = fmaf(S2[lane],      inv, b2s[lane]);
        const float a1 = fmaf(S2[lane + 32], inv, b2s[lane + 32]);
        for (int tt = w; tt < 13; tt += 8) {
            const int n0 = tt * 16;
            unsigned long long acc0[8], acc1[8];
            #pragma unroll
            for (int r = 0; r < 8; ++r) { acc0[r] = 0ull; acc1[r] = 0ull; }
            const float* hb = bufT + n0;
            #pragma unroll 8
            for (int k = 0; k < 64; ++k) {
                unsigned long long pa, pb;
                PACK2(pa, W2s[k * 64 + lane]);
                PACK2(pb, W2s[k * 64 + lane + 32]);
                const float* hr = hb + k * NS;
                ulonglong2 hA = *(const ulonglong2*)(hr);
                ulonglong2 hB = *(const ulonglong2*)(hr + 4);
                ulonglong2 hC = *(const ulonglong2*)(hr + 8);
                ulonglong2 hD = *(const ulonglong2*)(hr + 12);
                FMA2(acc0[0], pa, hA.x); FMA2(acc0[1], pa, hA.y);
                FMA2(acc0[2], pa, hB.x); FMA2(acc0[3], pa, hB.y);
                FMA2(acc0[4], pa, hC.x); FMA2(acc0[5], pa, hC.y);
                FMA2(acc0[6], pa, hD.x); FMA2(acc0[7], pa, hD.y);
                FMA2(acc1[0], pb, hA.x); FMA2(acc1[1], pb, hA.y);
                FMA2(acc1[2], pb, hB.x); FMA2(acc1[3], pb, hB.y);
                FMA2(acc1[4], pb, hC.x); FMA2(acc1[5], pb, hC.y);
                FMA2(acc1[6], pb, hD.x); FMA2(acc1[7], pb, hD.y);
            }
            #pragma unroll
            for (int r = 0; r < 8; ++r) {
                float z0, z1, y0, y1;
                UNPK2(z0, z1, acc0[r]);
                UNPK2(y0, y1, acc1[r]);
                int n = n0 + 2 * r;
                if (n < Nn) {
                    float* op = &g_h2[((size_t)(b * Nn + n) * Tn + t) * Hd];
                    op[lane]      = fmaxf(fmaf(z0, inv, a0), 0.f);
                    op[lane + 32] = fmaxf(fmaf(y0, inv, a1), 0.f);
                }
                if (n + 1 < Nn) {
                    float* op = &g_h2[((size_t)(b * Nn + n + 1) * Tn + t) * Hd];
                    op[lane]      = fmaxf(fmaf(z1, inv, a0), 0.f);
                    op[lane + 32] = fmaxf(fmaf(y1, inv, a1), 0.f);
                }
            }
        }
    }
}

// =====================================================================
// Kernel 2: persistent warp-autonomous LSTM + final FC.
// 138 blocks x 384 threads; warp owns 8 seqs; lane owns units {l, l+32}.
// acc[g][s] packs the unit-pair; x/h staged DUPLICATED in smem so the
// per-seq broadcast operand needs no MOVs.
// =====================================================================
#define WARPS 12
#define BLKT  (WARPS * 32)
#define SPW   8
#define SPB   (WARPS * SPW)     // 96
#define NBLK  138               // 138*96 == 13248

__global__ void __launch_bounds__(BLKT, 1) lstm_kernel(
    const float* __restrict__ Wih, const float* __restrict__ Whh,
    const float* __restrict__ bih, const float* __restrict__ bhh,
    const float* __restrict__ Wfc, const float* __restrict__ bfc,
    float* __restrict__ out)
{
    extern __shared__ float sm[];
    // 4 arrays of [64][32] float4: WiP1(g0,g1), WiP2(g2,g3), WhP1, WhP2
    float* Wp    = sm;                  // 32768
    float* bias  = Wp + 32768;          // 256
    float* wfcs  = bias + 256;          // 64
    float* stage = wfcs + 64;           // WARPS * 2048 (xd 1024 | hd 1024)

    const int tid = threadIdx.x;
    for (int i = tid; i < 32768; i += BLKT) {
        int arr = i >> 13;              // 0..3
        int r = i & 8191;
        int k = r >> 7;
        int l5 = (r >> 2) & 31;
        int c = r & 3;
        int g = ((arr & 1) << 1) + (c >> 1);
        int u = l5 + ((c & 1) << 5);
        const float* src = (arr < 2) ? Wih : Whh;
        Wp[i] = src[(g * 64 + u) * 64 + k];
    }
    for (int i = tid; i < 256; i += BLKT) bias[i] = bih[i] + bhh[i];
    if (tid < 64) wfcs[tid] = Wfc[tid];

    const int w = tid >> 5, lane = tid & 31;
    float* xd = stage + w * 2048;       // [64 k][16: 8 dup pairs]
    float* hd = xd + 1024;
    const int seq0 = blockIdx.x * SPB + w * SPW;

    for (int i = lane; i < 1024; i += 32) hd[i] = 0.f;
    __syncthreads();

    float brh[2][4];
    #pragma unroll
    for (int uu = 0; uu < 2; ++uu)
        #pragma unroll
        for (int g = 0; g < 4; ++g) {
            float bb = bias[g * 64 + uu * 32 + lane];
            brh[uu][g] = (g == 2) ? bb : 0.5f * bb;
        }

    float c0[8], c1[8];
    #pragma unroll
    for (int s = 0; s < 8; ++s) { c0[s] = 0.f; c1[s] = 0.f; }

    const float* WiP1 = Wp;
    const float* WiP2 = Wp + 8192;
    const float* WhP1 = Wp + 16384;
    const float* WhP2 = Wp + 24576;

    // prefetch t=0 x into registers (column j = lane / lane+32, 8 seqs)
    float4 px[2][2];
    {
        const float* gp0 = g_h2 + ((size_t)seq0 * Tn + 0) * Hd;
        #pragma unroll
        for (int uu = 0; uu < 2; ++uu) {
            const float* gp = gp0 + uu * 32 + lane;
            px[uu][0] = make_float4(gp[0*3072], gp[1*3072], gp[2*3072], gp[3*3072]);
            px[uu][1] = make_float4(gp[4*3072], gp[5*3072], gp[6*3072], gp[7*3072]);
        }
    }

    for (int t = 0; t < Tn; ++t) {
        // store prefetched x (duplicated) to rows lane / lane+32
        #pragma unroll
        for (int uu = 0; uu < 2; ++uu) {
            float* row = xd + (uu * 32 + lane) * 16;
            float4 a = px[uu][0], bq = px[uu][1];
            *(float4*)(row)      = make_float4(a.x, a.x, a.y, a.y);
            *(float4*)(row + 4)  = make_float4(a.z, a.z, a.w, a.w);
            *(float4*)(row + 8)  = make_float4(bq.x, bq.x, bq.y, bq.y);
            *(float4*)(row + 12) = make_float4(bq.z, bq.z, bq.w, bq.w);
        }
        __syncwarp();

        if (t + 1 < Tn) {   // prefetch next t during the k-loop
            const float* gp0 = g_h2 + ((size_t)seq0 * Tn + (t + 1)) * Hd;
            #pragma unroll
            for (int uu = 0; uu < 2; ++uu) {
                const float* gp = gp0 + uu * 32 + lane;
                px[uu][0] = make_float4(gp[0*3072], gp[1*3072], gp[2*3072], gp[3*3072]);
                px[uu][1] = make_float4(gp[4*3072], gp[5*3072], gp[6*3072], gp[7*3072]);
            }
        }

        unsigned long long acc[4][8];
        #pragma unroll
        for (int g = 0; g < 4; ++g)
            #pragma unroll
            for (int s = 0; s < 8; ++s) acc[g][s] = 0ull;

        #pragma unroll 8
        for (int k = 0; k < 64; ++k) {
            const int wb = (k << 7) + (lane << 2);
            ulonglong2 wi1 = *(const ulonglong2*)(WiP1 + wb);  // .x=g0 pair, .y=g1
            ulonglong2 wi2 = *(const ulonglong2*)(WiP2 + wb);  // .x=g2, .y=g3
            ulonglong2 wh1 = *(const ulonglong2*)(WhP1 + wb);
            ulonglong2 wh2 = *(const ulonglong2*)(WhP2 + wb);
            const float* xr = xd + (k << 4);
            const float* hr = hd + (k << 4);
            ulonglong2 xA = *(const ulonglong2*)(xr);
            ulonglong2 xB = *(const ulonglong2*)(xr + 4);
            ulonglong2 xC = *(const ulonglong2*)(xr + 8);
            ulonglong2 xD = *(const ulonglong2*)(xr + 12);
            ulonglong2 hA = *(const ulonglong2*)(hr);
            ulonglong2 hB = *(const ulonglong2*)(hr + 4);
            ulonglong2 hC = *(const ulonglong2*)(hr + 8);
            ulonglong2 hD = *(const ulonglong2*)(hr + 12);

            #define GK(g, WI, WH) \
                FMA2(acc[g][0], WI, xA.x); FMA2(acc[g][1], WI, xA.y); \
                FMA2(acc[g][2], WI, xB.x); FMA2(acc[g][3], WI, xB.y); \
                FMA2(acc[g][4], WI, xC.x); FMA2(acc[g][5], WI, xC.y); \
                FMA2(acc[g][6], WI, xD.x); FMA2(acc[g][7], WI, xD.y); \
                FMA2(acc[g][0], WH, hA.x); FMA2(acc[g][1], WH, hA.y); \
                FMA2(acc[g][2], WH, hB.x); FMA2(acc[g][3], WH, hB.y); \
                FMA2(acc[g][4], WH, hC.x); FMA2(acc[g][5], WH, hC.y); \
                FMA2(acc[g][6], WH, hD.x); FMA2(acc[g][7], WH, hD.y);

            GK(0, wi1.x, wh1.x)
            GK(1, wi1.y, wh1.y)
            GK(2, wi2.x, wh2.x)
            GK(3, wi2.y, wh2.y)
            #undef GK
        }
        __syncwarp();

        float hv0[8], hv1[8];
        #pragma unroll
        for (int s = 0; s < 8; ++s) {
            float i0, i1, f0, f1, g0, g1, o0, o1;
            UNPK2(i0, i1, acc[0][s]);
            UNPK2(f0, f1, acc[1][s]);
            UNPK2(g0, g1, acc[2][s]);
            UNPK2(o0, o1, acc[3][s]);
            {
                float ig = sigm2(i0, brh[0][0]);
                float fg = sigm2(f0, brh[0][1]);
                float gg = tanhm(g0 + brh[0][2]);
                float og = sigm2(o0, brh[0][3]);
                float cn = fmaf(fg, c0[s], ig * gg);
                c0[s] = cn;
                hv0[s] = og * tanhm(cn);
            }
            {
                float ig = sigm2(i1, brh[1][0]);
                float fg = sigm2(f1, brh[1][1]);
                float gg = tanhm(g1 + brh[1][2]);
                float og = sigm2(o1, brh[1][3]);
                float cn = fmaf(fg, c1[s], ig * gg);
                c1[s] = cn;
                hv1[s] = og * tanhm(cn);
            }
        }
        {
            float* r0 = hd + lane * 16;
            *(float4*)(r0)      = make_float4(hv0[0], hv0[0], hv0[1], hv0[1]);
            *(float4*)(r0 + 4)  = make_float4(hv0[2], hv0[2], hv0[3], hv0[3]);
            *(float4*)(r0 + 8)  = make_float4(hv0[4], hv0[4], hv0[5], hv0[5]);
            *(float4*)(r0 + 12) = make_float4(hv0[6], hv0[6], hv0[7], hv0[7]);
            float* r1 = hd + (lane + 32) * 16;
            *(float4*)(r1)      = make_float4(hv1[0], hv1[0], hv1[1], hv1[1]);
            *(float4*)(r1 + 4)  = make_float4(hv1[2], hv1[2], hv1[3], hv1[3]);
            *(float4*)(r1 + 8)  = make_float4(hv1[4], hv1[4], hv1[5], hv1[5]);
            *(float4*)(r1 + 12) = make_float4(hv1[6], hv1[6], hv1[7], hv1[7]);
        }
    }
    __syncwarp();

    if (lane < SPW) {
        int seq = seq0 + lane;
        float a = bfc[0];
        #pragma unroll 8
        for (int j = 0; j < 64; ++j) a += hd[j * 16 + 2 * lane] * wfcs[j];
        out[seq] = a;
    }
}

// =====================================================================
extern "C" void kernel_launch(void* const* d_in, const int* in_sizes, int n_in,
                              void* d_out, int out_size)
{
    const float* x   = (const float*)d_in[0];
    // d_in[1], d_in[2] = N1, N2: structurally irrelevant (sigmoid > 0 everywhere)
    const float* W1  = (const float*)d_in[3];
    const float* b1  = (const float*)d_in[4];
    const float* W2  = (const float*)d_in[5];
    const float* b2  = (const float*)d_in[6];
    const float* Wih = (const float*)d_in[7];
    const float* Whh = (const float*)d_in[8];
    const float* bih = (const float*)d_in[9];
    const float* bhh = (const float*)d_in[10];
    const float* Wfc = (const float*)d_in[11];
    const float* bfc = (const float*)d_in[12];
    float* out = (float*)d_out;

    const size_t gcn_smem  = (size_t)(384 + 4096 + 64 * 5 + 8 + 256 + 1248 + 64 * NS) * 4u;
    const size_t lstm_smem = (size_t)(32768 + 256 + 64 + WARPS * 2048) * 4u;  // 230,656 B

    cudaFuncSetAttribute(gcn_kernel,  cudaFuncAttributeMaxDynamicSharedMemorySize, (int)gcn_smem);
    cudaFuncSetAttribute(lstm_kernel, cudaFuncAttributeMaxDynamicSharedMemorySize, (int)lstm_smem);

    gcn_kernel<<<dim3(Tn, Bn), 256, gcn_smem>>>(x, W1, b1, W2, b2);
    lstm_kernel<<<NBLK, BLKT, lstm_smem>>>(Wih, Whh, bih, bhh, Wfc, bfc, out);
}

// round 7
// speedup vs baseline: 1.1056x; 1.1056x over previous
#include <cuda_runtime.h>
#include <cstdint>

#define Bn   64
#define Nn   207
#define Tn   48
#define Fin  6
#define Hd   64
#define NSEQ (Bn * Nn)        // 13248

// scratch: GCN output / LSTM input, [seq][t][Hd]
__device__ float g_h2[(size_t)NSEQ * Tn * Hd];   // 162.8 MB

#define PACK2(d, s)    asm("mov.b64 %0, {%1, %1};" : "=l"(d) : "f"(s))
#define UNPK2(a, b, v) asm("mov.b64 {%0, %1}, %2;" : "=f"(a), "=f"(b) : "l"(v))
#define FMA2(acc, a, b) asm("fma.rn.f32x2 %0, %1, %2, %0;" : "+l"(acc) : "l"(a), "l"(b))

__device__ __forceinline__ float tanhm(float x) {
    float r; asm("tanh.approx.f32 %0, %1;" : "=f"(r) : "f"(x)); return r;
}
// sigmoid(x + b) with bh = 0.5*b precomputed
__device__ __forceinline__ float sigm2(float x, float bh) {
    return fmaf(tanhm(fmaf(x, 0.5f, bh)), 0.5f, 0.5f);
}

// bank-swizzled slot base for 64 rows x 8 floats (4-phase stores,
// uniform-address broadcast reads). Injective, 16B-aligned, range [0,512).
__device__ __forceinline__ int PJ(int j) {
    return ((j & 3) << 6) + (((j >> 2) & 7) << 3) + ((j >> 5) << 8);
}

// =====================================================================
// Kernel 1: fused 2-layer GCN (proven R2 version).  grid (Tn, Bn), 256 thr.
// A_hat[m][n] = (1 + (m==n)) / 208
// =====================================================================
#define NS 216   // padded row stride of bufT

__global__ void __launch_bounds__(256, 2) gcn_kernel(
    const float* __restrict__ x,  const float* __restrict__ W1,
    const float* __restrict__ b1, const float* __restrict__ W2,
    const float* __restrict__ b2)
{
    extern __shared__ float sm[];
    float* W1s  = sm;               // 384
    float* W2s  = W1s + 384;        // 4096
    float* b1s  = W2s + 4096;       // 64
    float* b2s  = b1s + 64;         // 64
    float* S1   = b2s + 64;         // 64
    float* SH   = S1 + 64;          // 64
    float* S2   = SH + 64;          // 64
    float* xsum = S2 + 64;          // 8
    float* part = xsum + 8;         // 256
    float* xs   = part + 256;       // 1248
    float* bufT = xs + 1248;        // 64 * NS

    const int t = blockIdx.x, b = blockIdx.y;
    const int tid = threadIdx.x;
    const float inv = 1.0f / 208.0f;

    for (int i = tid; i < 384;  i += 256) W1s[i] = W1[i];
    for (int i = tid; i < 4096; i += 256) W2s[i] = W2[i];
    if (tid < 64) { b1s[tid] = b1[tid]; b2s[tid] = b2[tid]; }
    {
        const float* xb = x + (size_t)b * (Nn * Tn * Fin) + t * Fin;
        for (int i = tid; i < Nn * Fin; i += 256) {
            int n = i / 6, f = i - n * 6;
            xs[i] = xb[n * (Tn * Fin) + f];
        }
    }
    __syncthreads();

    // xsum[f] = sum_n x[n][f]
    if (tid < 48) {
        int f = tid % 6, q = tid / 6;
        float s = 0.f;
        for (int n = q; n < Nn; n += 8) s += xs[n * 6 + f];
        part[tid] = s;
    }
    __syncthreads();
    if (tid < 6) {
        float s = 0.f;
        #pragma unroll
        for (int q = 0; q < 8; ++q) s += part[q * 6 + tid];
        xsum[tid] = s;
    }
    __syncthreads();
    // S1 = xsum @ W1
    if (tid < 64) {
        float s = 0.f;
        #pragma unroll
        for (int f = 0; f < 6; ++f) s += xsum[f] * W1s[f * 64 + tid];
        S1[tid] = s;
    }
    __syncthreads();

    // h1 = relu((z1 + S1)/208 + b1), stored transposed bufT[j][n]
    {
        int j = tid >> 2, q = tid & 3;
        float w0 = W1s[j], w1 = W1s[64 + j], w2 = W1s[128 + j];
        float w3 = W1s[192 + j], w4 = W1s[256 + j], w5 = W1s[320 + j];
        float cj = fmaf(S1[j], inv, b1s[j]);
        float* row = bufT + j * NS;
        for (int n = q; n < Nn; n += 4) {
            const float* xr = xs + n * 6;
            float v = xr[0] * w0 + xr[1] * w1 + xr[2] * w2
                    + xr[3] * w3 + xr[4] * w4 + xr[5] * w5;
            row[n] = fmaxf(fmaf(v, inv, cj), 0.f);
        }
    }
    __syncthreads();

    // SH[j] = sum_n h1[j][n]
    {
        int j = tid >> 2, q = tid & 3;
        const float* row = bufT + j * NS;
        float s = 0.f;
        for (int n = q; n < Nn; n += 4) s += row[n];
        part[q * 64 + j] = s;
    }
    __syncthreads();
    if (tid < 64) SH[tid] = part[tid] + part[64 + tid] + part[128 + tid] + part[192 + tid];
    __syncthreads();
    // S2 = SH @ W2
    if (tid < 64) {
        float s = 0.f;
        #pragma unroll 8
        for (int k = 0; k < 64; ++k) s += SH[k] * W2s[k * 64 + tid];
        S2[tid] = s;
    }
    __syncthreads();

    // z2 = h1 @ W2 ; h2 = relu((z2 + S2)/208 + b2) -> global
    {
        const int w = tid >> 5, lane = tid & 31;
        const int j = 2 * lane;
        const float a0 = fmaf(S2[j],     inv, b2s[j]);
        const float a1 = fmaf(S2[j + 1], inv, b2s[j + 1]);
        for (int tt = w; tt < 26; tt += 8) {
            const int n0 = tt * 8;
            const int nv = (n0 + 8 <= Nn) ? 8 : (Nn - n0);
            unsigned long long acc[8];
            #pragma unroll
            for (int r = 0; r < 8; ++r) acc[r] = 0ull;
            const float* hb = bufT + n0;
            #pragma unroll 16
            for (int k = 0; k < 64; ++k) {
                float4 hA = *(const float4*)(hb + k * NS);
                float4 hB = *(const float4*)(hb + k * NS + 4);
                unsigned long long wv = *(const unsigned long long*)(W2s + k * 64 + j);
                unsigned long long p;
                PACK2(p, hA.x); FMA2(acc[0], wv, p);
                PACK2(p, hA.y); FMA2(acc[1], wv, p);
                PACK2(p, hA.z); FMA2(acc[2], wv, p);
                PACK2(p, hA.w); FMA2(acc[3], wv, p);
                PACK2(p, hB.x); FMA2(acc[4], wv, p);
                PACK2(p, hB.y); FMA2(acc[5], wv, p);
                PACK2(p, hB.z); FMA2(acc[6], wv, p);
                PACK2(p, hB.w); FMA2(acc[7], wv, p);
            }
            #pragma unroll
            for (int r = 0; r < 8; ++r) {
                if (r < nv) {
                    float z0, z1; UNPK2(z0, z1, acc[r]);
                    float2 o;
                    o.x = fmaxf(fmaf(z0, inv, a0), 0.f);
                    o.y = fmaxf(fmaf(z1, inv, a1), 0.f);
                    *(float2*)&g_h2[((size_t)(b * Nn + n0 + r) * Tn + t) * Hd + j] = o;
                }
            }
        }
    }
}

// =====================================================================
// Kernel 2: persistent warp-autonomous LSTM + final FC.
// 138 blocks x 512 threads (16 warps); warp owns 6 seqs; lane owns
// units {l, l+32}. 4 warps/SMSP for latency hiding.
// =====================================================================
#define WARPS 16
#define BLKT  (WARPS * 32)      // 512
#define SPW   6
#define SPB   (WARPS * SPW)     // 96
#define NBLK  138               // 138*96 == 13248 exactly

__global__ void __launch_bounds__(BLKT, 1) lstm_kernel(
    const float* __restrict__ Wih, const float* __restrict__ Whh,
    const float* __restrict__ bih, const float* __restrict__ bhh,
    const float* __restrict__ Wfc, const float* __restrict__ bfc,
    float* __restrict__ out)
{
    extern __shared__ float sm[];
    // 4 arrays of [64][32] float4: WiP1(g0,g1), WiP2(g2,g3), WhP1, WhP2
    // float4 c-layout: c=0..3 -> g = base_g + (c>>1), u = lane + (c&1)*32
    float* Wp    = sm;                  // 32768
    float* bias  = Wp + 32768;          // 256
    float* wfcs  = bias + 256;          // 64
    float* stage = wfcs + 64;           // WARPS * 1024 (xs 512 | hs 512)

    const int tid = threadIdx.x;
    for (int i = tid; i < 32768; i += BLKT) {
        int arr = i >> 13;              // 0..3
        int r = i & 8191;
        int k = r >> 7;
        int l5 = (r >> 2) & 31;
        int c = r & 3;
        int g = ((arr & 1) << 1) + (c >> 1);
        int u = l5 + ((c & 1) << 5);
        const float* src = (arr < 2) ? Wih : Whh;
        Wp[i] = src[(g * 64 + u) * 64 + k];
    }
    for (int i = tid; i < 256; i += BLKT) bias[i] = bih[i] + bhh[i];
    if (tid < 64) wfcs[tid] = Wfc[tid];

    const int w = tid >> 5, lane = tid & 31;
    float* xs = stage + w * 1024;
    float* hs = xs + 512;
    const int seq0 = blockIdx.x * SPB + w * SPW;

    // zero this warp's xs+hs (512 floats each — NOT 1024, that was the R6 OOB)
    for (int i = lane; i < 512; i += 32) { xs[i] = 0.f; hs[i] = 0.f; }
    __syncthreads();

    float brh[2][4];
    #pragma unroll
    for (int uu = 0; uu < 2; ++uu)
        #pragma unroll
        for (int g = 0; g < 4; ++g) {
            float bb = bias[g * 64 + uu * 32 + lane];
            brh[uu][g] = (g == 2) ? bb : 0.5f * bb;
        }

    float c0[SPW], c1[SPW];
    #pragma unroll
    for (int s = 0; s < SPW; ++s) { c0[s] = 0.f; c1[s] = 0.f; }

    const float* WiP1 = Wp;
    const float* WiP2 = Wp + 8192;
    const float* WhP1 = Wp + 16384;
    const float* WhP2 = Wp + 24576;

    const int pj0 = PJ(lane), pj1 = PJ(lane + 32);

    // prefetch t=0 x: column j = lane / lane+32, 6 seqs (stride Tn*Hd = 3072)
    float px[2][SPW];
    {
        const float* gp0 = g_h2 + ((size_t)seq0 * Tn + 0) * Hd;
        #pragma unroll
        for (int uu = 0; uu < 2; ++uu) {
            const float* gp = gp0 + uu * 32 + lane;
            #pragma unroll
            for (int s = 0; s < SPW; ++s) px[uu][s] = gp[s * 3072];
        }
    }

    for (int t = 0; t < Tn; ++t) {
        // store prefetched x into swizzled [j][slot] layout
        #pragma unroll
        for (int uu = 0; uu < 2; ++uu) {
            float* row = xs + (uu ? pj1 : pj0);
            *(float4*)(row)     = make_float4(px[uu][0], px[uu][1], px[uu][2], px[uu][3]);
            *(float2*)(row + 4) = make_float2(px[uu][4], px[uu][5]);
        }
        __syncwarp();

        if (t + 1 < Tn) {   // prefetch next t during the k-loop
            const float* gp0 = g_h2 + ((size_t)seq0 * Tn + (t + 1)) * Hd;
            #pragma unroll
            for (int uu = 0; uu < 2; ++uu) {
                const float* gp = gp0 + uu * 32 + lane;
                #pragma unroll
                for (int s = 0; s < SPW; ++s) px[uu][s] = gp[s * 3072];
            }
        }

        unsigned long long acc[2][4][3];
        #pragma unroll
        for (int uu = 0; uu < 2; ++uu)
            #pragma unroll
            for (int g = 0; g < 4; ++g)
                #pragma unroll
                for (int sp = 0; sp < 3; ++sp) acc[uu][g][sp] = 0ull;

        #pragma unroll 8
        for (int k = 0; k < 64; ++k) {
            const int pk = PJ(k);
            ulonglong2 xA = *(const ulonglong2*)(xs + pk);       // pairs (0,1),(2,3)
            unsigned long long xB = *(const unsigned long long*)(xs + pk + 4); // (4,5)
            ulonglong2 hA = *(const ulonglong2*)(hs + pk);
            unsigned long long hB = *(const unsigned long long*)(hs + pk + 4);
            const float4 wiA = *(const float4*)(WiP1 + (k << 7) + (lane << 2));
            const float4 wiB = *(const float4*)(WiP2 + (k << 7) + (lane << 2));
            const float4 whA = *(const float4*)(WhP1 + (k << 7) + (lane << 2));
            const float4 whB = *(const float4*)(WhP2 + (k << 7) + (lane << 2));

            unsigned long long p;
            // float4 c-layout: {g_a u0, g_a u1, g_{a+1} u0, g_{a+1} u1}
            #define DO_GU(uu, g, WI, WH) \
                PACK2(p, WI); \
                FMA2(acc[uu][g][0], p, xA.x); FMA2(acc[uu][g][1], p, xA.y); \
                FMA2(acc[uu][g][2], p, xB); \
                PACK2(p, WH); \
                FMA2(acc[uu][g][0], p, hA.x); FMA2(acc[uu][g][1], p, hA.y); \
                FMA2(acc[uu][g][2], p, hB);

            DO_GU(0, 0, wiA.x, whA.x)
            DO_GU(1, 0, wiA.y, whA.y)
            DO_GU(0, 1, wiA.z, whA.z)
            DO_GU(1, 1, wiA.w, whA.w)
            DO_GU(0, 2, wiB.x, whB.x)
            DO_GU(1, 2, wiB.y, whB.y)
            DO_GU(0, 3, wiB.z, whB.z)
            DO_GU(1, 3, wiB.w, whB.w)
            #undef DO_GU
        }
        __syncwarp();

        float hv0[SPW], hv1[SPW];
        #pragma unroll
        for (int sp = 0; sp < 3; ++sp) {
            float i0, i1, f0, f1, g0, g1, o0, o1;
            UNPK2(i0, i1, acc[0][0][sp]);
            UNPK2(f0, f1, acc[0][1][sp]);
            UNPK2(g0, g1, acc[0][2][sp]);
            UNPK2(o0, o1, acc[0][3][sp]);
            {
                int s = 2 * sp;
                float ig = sigm2(i0, brh[0][0]);
                float fg = sigm2(f0, brh[0][1]);
                float gg = tanhm(g0 + brh[0][2]);
                float og = sigm2(o0, brh[0][3]);
                float cn = fmaf(fg, c0[s], ig * gg);
                c0[s] = cn;
                hv0[s] = og * tanhm(cn);
            }
            {
                int s = 2 * sp + 1;
                float ig = sigm2(i1, brh[0][0]);
                float fg = sigm2(f1, brh[0][1]);
                float gg = tanhm(g1 + brh[0][2]);
                float og = sigm2(o1, brh[0][3]);
                float cn = fmaf(fg, c0[s], ig * gg);
                c0[s] = cn;
                hv0[s] = og * tanhm(cn);
            }
            UNPK2(i0, i1, acc[1][0][sp]);
            UNPK2(f0, f1, acc[1][1][sp]);
            UNPK2(g0, g1, acc[1][2][sp]);
            UNPK2(o0, o1, acc[1][3][sp]);
            {
                int s = 2 * sp;
                float ig = sigm2(i0, brh[1][0]);
                float fg = sigm2(f0, brh[1][1]);
                float gg = tanhm(g0 + brh[1][2]);
                float og = sigm2(o0, brh[1][3]);
                float cn = fmaf(fg, c1[s], ig * gg);
                c1[s] = cn;
                hv1[s] = og * tanhm(cn);
            }
            {
                int s = 2 * sp + 1;
                float ig = sigm2(i1, brh[1][0]);
                float fg = sigm2(f1, brh[1][1]);
                float gg = tanhm(g1 + brh[1][2]);
                float og = sigm2(o1, brh[1][3]);
                float cn = fmaf(fg, c1[s], ig * gg);
                c1[s] = cn;
                hv1[s] = og * tanhm(cn);
            }
        }
        {
            float* r0 = hs + pj0;
            *(float4*)(r0)     = make_float4(hv0[0], hv0[1], hv0[2], hv0[3]);
            *(float2*)(r0 + 4) = make_float2(hv0[4], hv0[5]);
            float* r1 = hs + pj1;
            *(float4*)(r1)     = make_float4(hv1[0], hv1[1], hv1[2], hv1[3]);
            *(float2*)(r1 + 4) = make_float2(hv1[4], hv1[5]);
        }
        // next iteration's post-x-store __syncwarp orders these h writes
        // before the next k-loop reads them.
    }
    __syncwarp();

    // final FC: out[seq] = h_T . W_fc + b_fc
    if (lane < SPW) {
        int seq = seq0 + lane;
        float a = bfc[0];
        #pragma unroll 8
        for (int j = 0; j < 64; ++j) a += hs[PJ(j) + lane] * wfcs[j];
        out[seq] = a;
    }
}

// =====================================================================
extern "C" void kernel_launch(void* const* d_in, const int* in_sizes, int n_in,
                              void* d_out, int out_size)
{
    const float* x   = (const float*)d_in[0];
    // d_in[1], d_in[2] = N1, N2: structurally irrelevant (sigmoid > 0 everywhere)
    const float* W1  = (const float*)d_in[3];
    const float* b1  = (const float*)d_in[4];
    const float* W2  = (const float*)d_in[5];
    const float* b2  = (const float*)d_in[6];
    const float* Wih = (const float*)d_in[7];
    const float* Whh = (const float*)d_in[8];
    const float* bih = (const float*)d_in[9];
    const float* bhh = (const float*)d_in[10];
    const float* Wfc = (const float*)d_in[11];
    const float* bfc = (const float*)d_in[12];
    float* out = (float*)d_out;

    const size_t gcn_smem  = (size_t)(384 + 4096 + 64 * 5 + 8 + 256 + 1248 + 64 * NS) * 4u;
    const size_t lstm_smem = (size_t)(32768 + 256 + 64 + WARPS * 1024) * 4u;  // 197,888 B

    cudaFuncSetAttribute(gcn_kernel,  cudaFuncAttributeMaxDynamicSharedMemorySize, (int)gcn_smem);
    cudaFuncSetAttribute(lstm_kernel, cudaFuncAttributeMaxDynamicSharedMemorySize, (int)lstm_smem);

    gcn_kernel<<<dim3(Tn, Bn), 256, gcn_smem>>>(x, W1, b1, W2, b2);
    lstm_kernel<<<NBLK, BLKT, lstm_smem>>>(Wih, Whh, bih, bhh, Wfc, bfc, out);
}

// round 8
// speedup vs baseline: 1.7997x; 1.6278x over previous
#include <cuda_runtime.h>
#include <cuda_bf16.h>
#include <cstdint>

#define Bn   64
#define Nn   207
#define Tn   48
#define Fin  6
#define Hd   64
#define NSEQ (Bn * Nn)        // 13248

// scratch: GCN output / LSTM input, [seq][t][Hd]
__device__ float g_h2[(size_t)NSEQ * Tn * Hd];   // 162.8 MB

#define PACK2(d, s)    asm("mov.b64 %0, {%1, %1};" : "=l"(d) : "f"(s))
#define UNPK2(a, b, v) asm("mov.b64 {%0, %1}, %2;" : "=f"(a), "=f"(b) : "l"(v))
#define FMA2(acc, a, b) asm("fma.rn.f32x2 %0, %1, %2, %0;" : "+l"(acc) : "l"(a), "l"(b))

__device__ __forceinline__ float tanhm(float x) {
    float r; asm("tanh.approx.f32 %0, %1;" : "=f"(r) : "f"(x)); return r;
}
// sigmoid(x + b) with bh = 0.5*b precomputed
__device__ __forceinline__ float sigm2(float x, float bh) {
    return fmaf(tanhm(fmaf(x, 0.5f, bh)), 0.5f, 0.5f);
}
__device__ __forceinline__ uint32_t smem_u32(const void* p) {
    uint32_t a;
    asm("{ .reg .u64 t; cvta.to.shared.u64 t, %1; cvt.u32.u64 %0, t; }" : "=r"(a) : "l"(p));
    return a;
}

// =====================================================================
// Kernel 1: fused 2-layer GCN (proven R2/R7 version).  grid (Tn, Bn).
// A_hat[m][n] = (1 + (m==n)) / 208
// =====================================================================
#define NS 216   // padded row stride of bufT

__global__ void __launch_bounds__(256, 2) gcn_kernel(
    const float* __restrict__ x,  const float* __restrict__ W1,
    const float* __restrict__ b1, const float* __restrict__ W2,
    const float* __restrict__ b2)
{
    extern __shared__ float sm[];
    float* W1s  = sm;               // 384
    float* W2s  = W1s + 384;        // 4096
    float* b1s  = W2s + 4096;       // 64
    float* b2s  = b1s + 64;         // 64
    float* S1   = b2s + 64;         // 64
    float* SH   = S1 + 64;          // 64
    float* S2   = SH + 64;          // 64
    float* xsum = S2 + 64;          // 8
    float* part = xsum + 8;         // 256
    float* xs   = part + 256;       // 1248
    float* bufT = xs + 1248;        // 64 * NS

    const int t = blockIdx.x, b = blockIdx.y;
    const int tid = threadIdx.x;
    const float inv = 1.0f / 208.0f;

    for (int i = tid; i < 384;  i += 256) W1s[i] = W1[i];
    for (int i = tid; i < 4096; i += 256) W2s[i] = W2[i];
    if (tid < 64) { b1s[tid] = b1[tid]; b2s[tid] = b2[tid]; }
    {
        const float* xb = x + (size_t)b * (Nn * Tn * Fin) + t * Fin;
        for (int i = tid; i < Nn * Fin; i += 256) {
            int n = i / 6, f = i - n * 6;
            xs[i] = xb[n * (Tn * Fin) + f];
        }
    }
    __syncthreads();

    if (tid < 48) {
        int f = tid % 6, q = tid / 6;
        float s = 0.f;
        for (int n = q; n < Nn; n += 8) s += xs[n * 6 + f];
        part[tid] = s;
    }
    __syncthreads();
    if (tid < 6) {
        float s = 0.f;
        #pragma unroll
        for (int q = 0; q < 8; ++q) s += part[q * 6 + tid];
        xsum[tid] = s;
    }
    __syncthreads();
    if (tid < 64) {
        float s = 0.f;
        #pragma unroll
        for (int f = 0; f < 6; ++f) s += xsum[f] * W1s[f * 64 + tid];
        S1[tid] = s;
    }
    __syncthreads();

    {
        int j = tid >> 2, q = tid & 3;
        float w0 = W1s[j], w1 = W1s[64 + j], w2 = W1s[128 + j];
        float w3 = W1s[192 + j], w4 = W1s[256 + j], w5 = W1s[320 + j];
        float cj = fmaf(S1[j], inv, b1s[j]);
        float* row = bufT + j * NS;
        for (int n = q; n < Nn; n += 4) {
            const float* xr = xs + n * 6;
            float v = xr[0] * w0 + xr[1] * w1 + xr[2] * w2
                    + xr[3] * w3 + xr[4] * w4 + xr[5] * w5;
            row[n] = fmaxf(fmaf(v, inv, cj), 0.f);
        }
    }
    __syncthreads();

    {
        int j = tid >> 2, q = tid & 3;
        const float* row = bufT + j * NS;
        float s = 0.f;
        for (int n = q; n < Nn; n += 4) s += row[n];
        part[q * 64 + j] = s;
    }
    __syncthreads();
    if (tid < 64) SH[tid] = part[tid] + part[64 + tid] + part[128 + tid] + part[192 + tid];
    __syncthreads();
    if (tid < 64) {
        float s = 0.f;
        #pragma unroll 8
        for (int k = 0; k < 64; ++k) s += SH[k] * W2s[k * 64 + tid];
        S2[tid] = s;
    }
    __syncthreads();

    {
        const int w = tid >> 5, lane = tid & 31;
        const int j = 2 * lane;
        const float a0 = fmaf(S2[j],     inv, b2s[j]);
        const float a1 = fmaf(S2[j + 1], inv, b2s[j + 1]);
        for (int tt = w; tt < 26; tt += 8) {
            const int n0 = tt * 8;
            const int nv = (n0 + 8 <= Nn) ? 8 : (Nn - n0);
            unsigned long long acc[8];
            #pragma unroll
            for (int r = 0; r < 8; ++r) acc[r] = 0ull;
            const float* hb = bufT + n0;
            #pragma unroll 16
            for (int k = 0; k < 64; ++k) {
                float4 hA = *(const float4*)(hb + k * NS);
                float4 hB = *(const float4*)(hb + k * NS + 4);
                unsigned long long wv = *(const unsigned long long*)(W2s + k * 64 + j);
                unsigned long long p;
                PACK2(p, hA.x); FMA2(acc[0], wv, p);
                PACK2(p, hA.y); FMA2(acc[1], wv, p);
                PACK2(p, hA.z); FMA2(acc[2], wv, p);
                PACK2(p, hA.w); FMA2(acc[3], wv, p);
                PACK2(p, hB.x); FMA2(acc[4], wv, p);
                PACK2(p, hB.y); FMA2(acc[5], wv, p);
                PACK2(p, hB.z); FMA2(acc[6], wv, p);
                PACK2(p, hB.w); FMA2(acc[7], wv, p);
            }
            #pragma unroll
            for (int r = 0; r < 8; ++r) {
                if (r < nv) {
                    float z0, z1; UNPK2(z0, z1, acc[r]);
                    float2 o;
                    o.x = fmaxf(fmaf(z0, inv, a0), 0.f);
                    o.y = fmaxf(fmaf(z1, inv, a1), 0.f);
                    *(float2*)&g_h2[((size_t)(b * Nn + n0 + r) * Tn + t) * Hd + j] = o;
                }
            }
        }
    }
}

// =====================================================================
// Kernel 2: HMMA (mma.sync bf16, 3-term compensated) LSTM + FC.
// 138 CTAs x 384 threads (12 warps); M=96 seqs/CTA (exact cover).
// Per step: C[96,256] = A[96,128] @ B[128,256], A = [x_t | h] hi/lo bf16,
// B = [Wih | Whh]^T cols permuted n=(u<<2)|g so each C-tile holds all 4
// gates of a unit pair. fp32 c-state in regs; h fed back as bf16 hi/lo.
// =====================================================================
#define LNB  138
#define LNT  384
#define MROW 96
#define ARS  272           // padded byte row stride (17*16B) — ldmatrix conflict-free

// smem byte offsets
#define O_AHI  0                       // 96*272  = 26112
#define O_ALO  26112                   // 26112
#define O_BHI  52224                   // 256*272 = 69632
#define O_BLO  121856                  // 69632
#define O_BIAS 191488                  // 256*4
#define O_WFC  192512                  // 64*4
#define O_FCP  192768                  // 96*4
#define LSMEM  193152

#define LDSM4(R, a) asm volatile("ldmatrix.sync.aligned.m8n8.x4.shared.b16 {%0,%1,%2,%3}, [%4];" \
    : "=r"((R)[0]), "=r"((R)[1]), "=r"((R)[2]), "=r"((R)[3]) : "r"(a))
#define LDSM2(R, a) asm volatile("ldmatrix.sync.aligned.m8n8.x2.shared.b16 {%0,%1}, [%2];" \
    : "=r"((R)[0]), "=r"((R)[1]) : "r"(a))
#define MMA16816(C, A, B) asm volatile( \
    "mma.sync.aligned.m16n8k16.row.col.f32.bf16.bf16.f32 " \
    "{%0,%1,%2,%3}, {%4,%5,%6,%7}, {%8,%9}, {%0,%1,%2,%3};" \
    : "+f"((C)[0]), "+f"((C)[1]), "+f"((C)[2]), "+f"((C)[3]) \
    : "r"((A)[0]), "r"((A)[1]), "r"((A)[2]), "r"((A)[3]), "r"((B)[0]), "r"((B)[1]))

__device__ __forceinline__ void bf16split(float v, unsigned short& h, unsigned short& l) {
    __nv_bfloat16 hb = __float2bfloat16(v);
    h = __bfloat16_as_ushort(hb);
    l = __bfloat16_as_ushort(__float2bfloat16(v - __bfloat162float(hb)));
}

// stage x_t (fp32 -> bf16 hi/lo) into A cols 0..63. 384 thr: row=tid>>2, 16 cols each.
__device__ __forceinline__ void stage_x(char* Ahi, char* Alo, int tid, int blk, int t) {
    const int row = tid >> 2, cq = tid & 3;
    const float* gp = g_h2 + ((size_t)(blk * MROW + row) * Tn + t) * Hd + cq * 16;
    float f[16];
    #pragma unroll
    for (int q = 0; q < 4; ++q) {
        float4 v = ((const float4*)gp)[q];
        f[4*q] = v.x; f[4*q+1] = v.y; f[4*q+2] = v.z; f[4*q+3] = v.w;
    }
    unsigned short hh[16], ll[16];
    #pragma unroll
    for (int e = 0; e < 16; ++e) bf16split(f[e], hh[e], ll[e]);
    const uint32_t off = (uint32_t)row * ARS + (uint32_t)cq * 32u;
    uint4 H0 = make_uint4((uint32_t)hh[0] | ((uint32_t)hh[1] << 16), (uint32_t)hh[2] | ((uint32_t)hh[3] << 16),
                          (uint32_t)hh[4] | ((uint32_t)hh[5] << 16), (uint32_t)hh[6] | ((uint32_t)hh[7] << 16));
    uint4 H1 = make_uint4((uint32_t)hh[8] | ((uint32_t)hh[9] << 16), (uint32_t)hh[10] | ((uint32_t)hh[11] << 16),
                          (uint32_t)hh[12] | ((uint32_t)hh[13] << 16), (uint32_t)hh[14] | ((uint32_t)hh[15] << 16));
    uint4 L0 = make_uint4((uint32_t)ll[0] | ((uint32_t)ll[1] << 16), (uint32_t)ll[2] | ((uint32_t)ll[3] << 16),
                          (uint32_t)ll[4] | ((uint32_t)ll[5] << 16), (uint32_t)ll[6] | ((uint32_t)ll[7] << 16));
    uint4 L1 = make_uint4((uint32_t)ll[8] | ((uint32_t)ll[9] << 16), (uint32_t)ll[10] | ((uint32_t)ll[11] << 16),
                          (uint32_t)ll[12] | ((uint32_t)ll[13] << 16), (uint32_t)ll[14] | ((uint32_t)ll[15] << 16));
    *(uint4*)(Ahi + off)      = H0;
    *(uint4*)(Ahi + off + 16) = H1;
    *(uint4*)(Alo + off)      = L0;
    *(uint4*)(Alo + off + 16) = L1;
}

__global__ void __launch_bounds__(LNT, 1) lstm_kernel(
    const float* __restrict__ Wih, const float* __restrict__ Whh,
    const float* __restrict__ bih, const float* __restrict__ bhh,
    const float* __restrict__ Wfc, const float* __restrict__ bfc,
    float* __restrict__ out)
{
    extern __shared__ char smc[];
    char*  Ahi   = smc + O_AHI;
    char*  Alo   = smc + O_ALO;
    char*  Bhi   = smc + O_BHI;
    char*  Blo   = smc + O_BLO;
    float* bias2 = (float*)(smc + O_BIAS);   // [u*4+g] = (g==2)? b : 0.5b
    float* wfcs  = (float*)(smc + O_WFC);
    float* fcp   = (float*)(smc + O_FCP);

    const int tid = threadIdx.x;

    // ---- stage weights B[n][k], n = (u<<2)|g, k<64: Wih, k>=64: Whh ----
    for (int i = tid; i < 256 * 128; i += LNT) {
        int n = i >> 7, k = i & 127;
        int u = n >> 2, g = n & 3;
        int rw = g * 64 + u;
        float v = (k < 64) ? Wih[rw * 64 + k] : Whh[rw * 64 + (k - 64)];
        unsigned short hh, ll;
        bf16split(v, hh, ll);
        uint32_t off = (uint32_t)n * ARS + (uint32_t)k * 2u;
        *(unsigned short*)(Bhi + off) = hh;
        *(unsigned short*)(Blo + off) = ll;
    }
    // zero A (x + h regions + pad) -> h0 = 0
    for (int i = tid; i < (MROW * ARS) / 4; i += LNT) {
        ((uint32_t*)Ahi)[i] = 0u;
        ((uint32_t*)Alo)[i] = 0u;
    }
    for (int i = tid; i < 256; i += LNT) {
        int u = i >> 2, g = i & 3;
        float b = bih[g * 64 + u] + bhh[g * 64 + u];
        bias2[i] = (g == 2) ? b : 0.5f * b;
    }
    if (tid < 64) wfcs[tid] = Wfc[tid];
    if (tid < MROW) fcp[tid] = 0.f;

    const int w = tid >> 5, lane = tid & 31;
    const int mp = w % 3;        // M-tile pair: rows 32mp..32mp+31
    const int nq = w / 3;        // 0..3: 32 n-columns per phase

    const uint32_t aHi = smem_u32(Ahi), aLo = smem_u32(Alo);
    const uint32_t bHi = smem_u32(Bhi), bLo = smem_u32(Blo);

    // ldmatrix lane address components
    const int ai  = lane >> 3;   // A x4 tile index 0..3
    const int arw = lane & 7;
    const uint32_t aRowOff = (uint32_t)(32 * mp + ((ai & 1) << 3) + arw) * ARS
                           + (uint32_t)((ai >> 1) << 4);
    const int bl  = lane & 15;
    const uint32_t bRowPart = (uint32_t)(bl & 7) * ARS + (uint32_t)(((bl >> 3) & 1) << 4);

    float cst[16];
    #pragma unroll
    for (int i = 0; i < 16; ++i) cst[i] = 0.f;
    uint32_t hpk[16];

    stage_x(Ahi, Alo, tid, blockIdx.x, 0);
    __syncthreads();

    for (int t = 0; t < Tn; ++t) {
        const bool last = (t == Tn - 1);
        #pragma unroll
        for (int p = 0; p < 2; ++p) {
            const int nbase = p * 128 + nq * 32;
            float C[8][4];
            #pragma unroll
            for (int i = 0; i < 8; ++i)
                #pragma unroll
                for (int j = 0; j < 4; ++j) C[i][j] = 0.f;

            #pragma unroll
            for (int ks = 0; ks < 8; ++ks) {
                const uint32_t kb = (uint32_t)ks * 32u;
                uint32_t Ah[2][4], Al[2][4], Bh[4][2], Bl[4][2];
                #pragma unroll
                for (int m = 0; m < 2; ++m) {
                    uint32_t ro = aRowOff + (uint32_t)(16 * m) * ARS + kb;
                    LDSM4(Ah[m], aHi + ro);
                    LDSM4(Al[m], aLo + ro);
                }
                #pragma unroll
                for (int nt = 0; nt < 4; ++nt) {
                    uint32_t ro = (uint32_t)(nbase + 8 * nt) * ARS + bRowPart + kb;
                    LDSM2(Bh[nt], bHi + ro);
                    LDSM2(Bl[nt], bLo + ro);
                }
                #pragma unroll
                for (int m = 0; m < 2; ++m)
                    #pragma unroll
                    for (int nt = 0; nt < 4; ++nt) {
                        MMA16816(C[m * 4 + nt], Ah[m], Bh[nt]);
                        MMA16816(C[m * 4 + nt], Al[m], Bh[nt]);
                        MMA16816(C[m * 4 + nt], Ah[m], Bl[nt]);
                    }
            }

            // epilogue: C-tile = 16 seqs x (2 units x 4 gates)
            #pragma unroll
            for (int m = 0; m < 2; ++m)
                #pragma unroll
                for (int nt = 0; nt < 4; ++nt) {
                    float c0 = C[m * 4 + nt][0], c1 = C[m * 4 + nt][1];
                    float c2 = C[m * 4 + nt][2], c3 = C[m * 4 + nt][3];
                    float sA = (lane & 1) ? c0 : c2;
                    float rA = __shfl_xor_sync(0xffffffffu, sA, 1);
                    float sB = (lane & 1) ? c1 : c3;
                    float rB = __shfl_xor_sync(0xffffffffu, sB, 1);
                    float gi, gf, gg, go;
                    if (!(lane & 1)) { gi = c0; gf = c1; gg = rA; go = rB; }
                    else             { gi = rA; gf = rB; gg = c2; go = c3; }
                    const int u = (nbase >> 2) + 2 * nt + ((lane & 2) >> 1);
                    float4 bb = *(const float4*)(bias2 + u * 4);
                    float ig = sigm2(gi, bb.x);
                    float fg = sigm2(gf, bb.y);
                    float g_ = tanhm(gg + bb.z);
                    float og = sigm2(go, bb.w);
                    const int ci = p * 8 + m * 4 + nt;
                    float cn = fmaf(fg, cst[ci], ig * g_);
                    cst[ci] = cn;
                    float hv = og * tanhm(cn);
                    unsigned short hh, ll;
                    bf16split(hv, hh, ll);
                    hpk[ci] = (uint32_t)hh | ((uint32_t)ll << 16);
                    if (last) {
                        int row = 32 * mp + 16 * m + (lane >> 2) + ((lane & 1) << 3);
                        atomicAdd(&fcp[row], hv * wfcs[u]);
                    }
                }
        }
        __syncthreads();   // all warps done reading A

        // write h_t (both phases) into A cols 64..127
        const int rowb = 32 * mp + (lane >> 2) + ((lane & 1) << 3);
        #pragma unroll
        for (int p = 0; p < 2; ++p)
            #pragma unroll
            for (int m = 0; m < 2; ++m)
                #pragma unroll
                for (int nt = 0; nt < 4; ++nt) {
                    const int ci = p * 8 + m * 4 + nt;
                    const int row = rowb + 16 * m;
                    const int u = p * 32 + nq * 8 + 2 * nt + ((lane & 2) >> 1);
                    const uint32_t off = (uint32_t)row * ARS + (uint32_t)(64 + u) * 2u;
                    uint32_t v = hpk[ci];
                    *(unsigned short*)(Ahi + off) = (unsigned short)(v & 0xffffu);
                    *(unsigned short*)(Alo + off) = (unsigned short)(v >> 16);
                }
        if (t + 1 < Tn) stage_x(Ahi, Alo, tid, blockIdx.x, t + 1);
        __syncthreads();   // A ready for next step
    }

    if (tid < MROW) out[blockIdx.x * MROW + tid] = fcp[tid] + bfc[0];
}

// =====================================================================
extern "C" void kernel_launch(void* const* d_in, const int* in_sizes, int n_in,
                              void* d_out, int out_size)
{
    const float* x   = (const float*)d_in[0];
    // d_in[1], d_in[2] = N1, N2: structurally irrelevant (sigmoid > 0 everywhere)
    const float* W1  = (const float*)d_in[3];
    const float* b1  = (const float*)d_in[4];
    const float* W2  = (const float*)d_in[5];
    const float* b2  = (const float*)d_in[6];
    const float* Wih = (const float*)d_in[7];
    const float* Whh = (const float*)d_in[8];
    const float* bih = (const float*)d_in[9];
    const float* bhh = (const float*)d_in[10];
    const float* Wfc = (const float*)d_in[11];
    const float* bfc = (const float*)d_in[12];
    float* out = (float*)d_out;

    const size_t gcn_smem  = (size_t)(384 + 4096 + 64 * 5 + 8 + 256 + 1248 + 64 * NS) * 4u;
    const size_t lstm_smem = (size_t)LSMEM;   // 193,152 B

    cudaFuncSetAttribute(gcn_kernel,  cudaFuncAttributeMaxDynamicSharedMemorySize, (int)gcn_smem);
    cudaFuncSetAttribute(lstm_kernel, cudaFuncAttributeMaxDynamicSharedMemorySize, (int)lstm_smem);

    gcn_kernel<<<dim3(Tn, Bn), 256, gcn_smem>>>(x, W1, b1, W2, b2);
    lstm_kernel<<<LNB, LNT, lstm_smem>>>(Wih, Whh, bih, bhh, Wfc, bfc, out);
}

// round 9
// speedup vs baseline: 1.8655x; 1.0365x over previous
#include <cuda_runtime.h>
#include <cuda_bf16.h>
#include <cstdint>

#define Bn   64
#define Nn   207
#define Tn   48
#define Fin  6
#define Hd   64
#define NSEQ (Bn * Nn)        // 13248

// scratch: GCN output / LSTM input, [seq][t][Hd]
__device__ float g_h2[(size_t)NSEQ * Tn * Hd];   // 162.8 MB

__device__ __forceinline__ float tanhm(float x) {
    float r; asm("tanh.approx.f32 %0, %1;" : "=f"(r) : "f"(x)); return r;
}
// sigmoid(x + b) with bh = 0.5*b precomputed
__device__ __forceinline__ float sigm2(float x, float bh) {
    return fmaf(tanhm(fmaf(x, 0.5f, bh)), 0.5f, 0.5f);
}
__device__ __forceinline__ uint32_t smem_u32(const void* p) {
    uint32_t a;
    asm("{ .reg .u64 t; cvta.to.shared.u64 t, %1; cvt.u32.u64 %0, t; }" : "=r"(a) : "l"(p));
    return a;
}

#define LDSM4(R, a) asm volatile("ldmatrix.sync.aligned.m8n8.x4.shared.b16 {%0,%1,%2,%3}, [%4];" \
    : "=r"((R)[0]), "=r"((R)[1]), "=r"((R)[2]), "=r"((R)[3]) : "r"(a))
#define LDSM2(R, a) asm volatile("ldmatrix.sync.aligned.m8n8.x2.shared.b16 {%0,%1}, [%2];" \
    : "=r"((R)[0]), "=r"((R)[1]) : "r"(a))
#define MMA16816(C, A, B) asm volatile( \
    "mma.sync.aligned.m16n8k16.row.col.f32.bf16.bf16.f32 " \
    "{%0,%1,%2,%3}, {%4,%5,%6,%7}, {%8,%9}, {%0,%1,%2,%3};" \
    : "+f"((C)[0]), "+f"((C)[1]), "+f"((C)[2]), "+f"((C)[3]) \
    : "r"((A)[0]), "r"((A)[1]), "r"((A)[2]), "r"((A)[3]), "r"((B)[0]), "r"((B)[1]))

__device__ __forceinline__ void bf16split(float v, unsigned short& h, unsigned short& l) {
    __nv_bfloat16 hb = __float2bfloat16(v);
    h = __bfloat16_as_ushort(hb);
    l = __bfloat16_as_ushort(__float2bfloat16(v - __bfloat162float(hb)));
}
__device__ __forceinline__ float bf16bits2f(uint32_t u) {
    return __uint_as_float(u << 16);
}

// =====================================================================
// Kernel 1: fused 2-layer GCN, z2 via HMMA.  grid (Tn, Bn), 256 thr.
// A_hat[m][n] = (1 + (m==n)) / 208
// =====================================================================
#define AR2 144          // A/B byte row stride (9*16B, ldsm conflict-free)
// smem byte offsets (floats region then bf16 tiles)
#define G_NFLT  6440     // W1s 384 | W2s 4096 | b1s 64 | b2s 64 | S1 64 | SH 64 |
                         // xsum 8 | part 256 | xs 1248 | cjs 64 | a2s 64 | (pad 64)
#define G_AHI   25760    // 208*144 = 29952
#define G_ALO   55712
#define G_BHI   85664    // 64*144 = 9216
#define G_BLO   94880
#define G_SMEM  104096

__global__ void __launch_bounds__(256, 2) gcn_kernel(
    const float* __restrict__ x,  const float* __restrict__ W1,
    const float* __restrict__ b1, const float* __restrict__ W2,
    const float* __restrict__ b2)
{
    extern __shared__ char smc[];
    float* fl   = (float*)smc;
    float* W1s  = fl;               // 384
    float* W2s  = W1s + 384;        // 4096
    float* b1s  = W2s + 4096;       // 64
    float* b2s  = b1s + 64;         // 64
    float* S1   = b2s + 64;         // 64
    float* SH   = S1 + 64;          // 64
    float* xsum = SH + 64;          // 8
    float* part = xsum + 8;         // 256
    float* xs   = part + 256;       // 1248
    float* cjs  = xs + 1248;        // 64
    float* a2s  = cjs + 64;         // 64
    char*  A2h  = smc + G_AHI;
    char*  A2l  = smc + G_ALO;
    char*  B2h  = smc + G_BHI;
    char*  B2l  = smc + G_BLO;

    const int t = blockIdx.x, b = blockIdx.y;
    const int tid = threadIdx.x;
    const int lane = tid & 31;
    const float inv = 1.0f / 208.0f;

    for (int i = tid; i < 384;  i += 256) W1s[i] = W1[i];
    for (int i = tid; i < 4096; i += 256) W2s[i] = W2[i];
    // B = W2^T-ish: B[n][k] = W2[k][n], bf16 hi/lo
    for (int i = tid; i < 4096; i += 256) {
        int n = i >> 6, k = i & 63;
        unsigned short hh, ll;
        bf16split(W2[k * 64 + n], hh, ll);
        uint32_t off = (uint32_t)n * AR2 + (uint32_t)k * 2u;
        *(unsigned short*)(B2h + off) = hh;
        *(unsigned short*)(B2l + off) = ll;
    }
    if (tid < 64) { b1s[tid] = b1[tid]; b2s[tid] = b2[tid]; }
    {
        const float* xb = x + (size_t)b * (Nn * Tn * Fin) + t * Fin;
        for (int i = tid; i < Nn * Fin; i += 256) {
            int n = i / 6, f = i - n * 6;
            xs[i] = xb[n * (Tn * Fin) + f];
        }
    }
    __syncthreads();

    // xsum[f] = sum_n x[n][f]
    if (tid < 48) {
        int f = tid % 6, q = tid / 6;
        float s = 0.f;
        for (int n = q; n < Nn; n += 8) s += xs[n * 6 + f];
        part[tid] = s;
    }
    __syncthreads();
    if (tid < 6) {
        float s = 0.f;
        #pragma unroll
        for (int q = 0; q < 8; ++q) s += part[q * 6 + tid];
        xsum[tid] = s;
    }
    __syncthreads();
    // S1 = xsum @ W1 ; cjs = S1*inv + b1
    if (tid < 64) {
        float s = 0.f;
        #pragma unroll
        for (int f = 0; f < 6; ++f) s += xsum[f] * W1s[f * 64 + tid];
        S1[tid] = s;
        cjs[tid] = fmaf(s, inv, b1s[tid]);
    }
    __syncthreads();

    // h1[n][j] = relu(z1*inv + cjs[j]) -> A (bf16 hi/lo), rotated col order
    if (tid < 208) {
        const int n = tid;
        float xr[6];
        #pragma unroll
        for (int f = 0; f < 6; ++f) xr[f] = (n < 207) ? xs[n * 6 + f] : 0.f;
        char* arh = A2h + (uint32_t)n * AR2;
        char* arl = A2l + (uint32_t)n * AR2;
        const int o = (lane >> 3) & 3;
        for (int s = 0; s < 32; ++s) {
            int wd = (o + s) & 31;
            int j = wd * 2;
            float v0 = xr[0] * W1s[j]       + xr[1] * W1s[64 + j]
                     + xr[2] * W1s[128 + j] + xr[3] * W1s[192 + j]
                     + xr[4] * W1s[256 + j] + xr[5] * W1s[320 + j];
            float v1 = xr[0] * W1s[j + 1]   + xr[1] * W1s[64 + j + 1]
                     + xr[2] * W1s[128 + j + 1] + xr[3] * W1s[192 + j + 1]
                     + xr[4] * W1s[256 + j + 1] + xr[5] * W1s[320 + j + 1];
            v0 = fmaxf(fmaf(v0, inv, cjs[j]), 0.f);
            v1 = fmaxf(fmaf(v1, inv, cjs[j + 1]), 0.f);
            unsigned short h0, l0, h1v, l1;
            bf16split(v0, h0, l0);
            bf16split(v1, h1v, l1);
            *(uint32_t*)(arh + j * 2) = (uint32_t)h0 | ((uint32_t)h1v << 16);
            *(uint32_t*)(arl + j * 2) = (uint32_t)l0 | ((uint32_t)l1 << 16);
        }
    }
    __syncthreads();

    // SH[j] = sum_n h1'[n][j] (from quantized A, consistent with MMA input)
    {
        int j = tid & 63, q = tid >> 6;
        float s = 0.f;
        for (int n = q; n < 207; n += 4) {
            uint32_t hh = *(const unsigned short*)(A2h + (uint32_t)n * AR2 + j * 2);
            uint32_t ll = *(const unsigned short*)(A2l + (uint32_t)n * AR2 + j * 2);
            s += bf16bits2f(hh) + bf16bits2f(ll);
        }
        part[q * 64 + j] = s;
    }
    __syncthreads();
    if (tid < 64) SH[tid] = part[tid] + part[64 + tid] + part[128 + tid] + part[192 + tid];
    __syncthreads();
    // a2s = (SH @ W2)*inv + b2
    if (tid < 64) {
        float s = 0.f;
        #pragma unroll 8
        for (int k = 0; k < 64; ++k) s += SH[k] * W2s[k * 64 + tid];
        a2s[tid] = fmaf(s, inv, b2s[tid]);
    }
    __syncthreads();

    // z2 via HMMA: C[208,64] = A[208,64] @ B[64,64], 3-term compensated
    {
        const int w = tid >> 5;
        const uint32_t aH = smem_u32(A2h), aL = smem_u32(A2l);
        const uint32_t bH = smem_u32(B2h), bL = smem_u32(B2l);
        const int ai = lane >> 3, arw = lane & 7;
        const int bl = lane & 15;
        const uint32_t bRowPart = (uint32_t)(bl & 7) * AR2 + (uint32_t)(((bl >> 3) & 1) << 4);

        #pragma unroll
        for (int rep = 0; rep < 2; ++rep) {
            const int mt = w + rep * 8;
            if (mt >= 13) break;
            float C[8][4];
            #pragma unroll
            for (int i = 0; i < 8; ++i)
                #pragma unroll
                for (int jj = 0; jj < 4; ++jj) C[i][jj] = 0.f;

            #pragma unroll
            for (int ks = 0; ks < 4; ++ks) {
                const uint32_t kb = (uint32_t)ks * 32u;
                uint32_t Ah[4], Al[4];
                uint32_t ro = (uint32_t)(mt * 16 + ((ai & 1) << 3) + arw) * AR2
                            + (uint32_t)((ai >> 1) << 4) + kb;
                LDSM4(Ah, aH + ro);
                LDSM4(Al, aL + ro);
                #pragma unroll
                for (int nt = 0; nt < 8; ++nt) {
                    uint32_t rb = (uint32_t)(nt * 8) * AR2 + bRowPart + kb;
                    uint32_t Bh[2], Bl2[2];
                    LDSM2(Bh, bH + rb);
                    LDSM2(Bl2, bL + rb);
                    MMA16816(C[nt], Ah, Bh);
                    MMA16816(C[nt], Al, Bh);
                    MMA16816(C[nt], Ah, Bl2);
                }
            }

            // epilogue: h2 = relu(z2*inv + a2s[j]) -> g_h2
            #pragma unroll
            for (int nt = 0; nt < 8; ++nt) {
                const int j = nt * 8 + 2 * (lane & 3);
                const float a0 = a2s[j], a1 = a2s[j + 1];
                const int r0 = mt * 16 + (lane >> 2);
                const int r1 = r0 + 8;
                if (r0 < Nn) {
                    float2 o;
                    o.x = fmaxf(fmaf(C[nt][0], inv, a0), 0.f);
                    o.y = fmaxf(fmaf(C[nt][1], inv, a1), 0.f);
                    *(float2*)&g_h2[((size_t)(b * Nn + r0) * Tn + t) * Hd + j] = o;
                }
                if (r1 < Nn) {
                    float2 o;
                    o.x = fmaxf(fmaf(C[nt][2], inv, a0), 0.f);
                    o.y = fmaxf(fmaf(C[nt][3], inv, a1), 0.f);
                    *(float2*)&g_h2[((size_t)(b * Nn + r1) * Tn + t) * Hd + j] = o;
                }
            }
        }
    }
}

// =====================================================================
// Kernel 2: HMMA LSTM + FC, shuffle-free epilogue.
// 138 CTAs x 384 threads (12 warps); M=96 seqs/CTA.
// B natural layout [g*64+u][k]; per phase each warp covers the SAME
// 8-unit slice across all 4 gate blocks -> gates are thread-local.
// =====================================================================
#define LNB  138
#define LNT  384
#define MROW 96
#define ARS  272

#define O_AHI  0                       // 96*272  = 26112
#define O_ALO  26112
#define O_BHI  52224                   // 256*272 = 69632
#define O_BLO  121856
#define O_BIAS 191488                  // 256*4
#define O_WFC  192512                  // 64*4
#define O_FCP  192768                  // 96*4
#define LSMEM  193152

// stage x_t (fp32 -> bf16 hi/lo) into A cols 0..63. 384 thr: row=tid>>2, 16 cols.
__device__ __forceinline__ void stage_x(char* Ahi, char* Alo, int tid, int blk, int t) {
    const int row = tid >> 2, cq = tid & 3;
    const float* gp = g_h2 + ((size_t)(blk * MROW + row) * Tn + t) * Hd + cq * 16;
    float f[16];
    #pragma unroll
    for (int q = 0; q < 4; ++q) {
        float4 v = ((const float4*)gp)[q];
        f[4*q] = v.x; f[4*q+1] = v.y; f[4*q+2] = v.z; f[4*q+3] = v.w;
    }
    unsigned short hh[16], ll[16];
    #pragma unroll
    for (int e = 0; e < 16; ++e) bf16split(f[e], hh[e], ll[e]);
    const uint32_t off = (uint32_t)row * ARS + (uint32_t)cq * 32u;
    uint4 H0 = make_uint4((uint32_t)hh[0] | ((uint32_t)hh[1] << 16), (uint32_t)hh[2] | ((uint32_t)hh[3] << 16),
                          (uint32_t)hh[4] | ((uint32_t)hh[5] << 16), (uint32_t)hh[6] | ((uint32_t)hh[7] << 16));
    uint4 H1 = make_uint4((uint32_t)hh[8] | ((uint32_t)hh[9] << 16), (uint32_t)hh[10] | ((uint32_t)hh[11] << 16),
                          (uint32_t)hh[12] | ((uint32_t)hh[13] << 16), (uint32_t)hh[14] | ((uint32_t)hh[15] << 16));
    uint4 L0 = make_uint4((uint32_t)ll[0] | ((uint32_t)ll[1] << 16), (uint32_t)ll[2] | ((uint32_t)ll[3] << 16),
                          (uint32_t)ll[4] | ((uint32_t)ll[5] << 16), (uint32_t)ll[6] | ((uint32_t)ll[7] << 16));
    uint4 L1 = make_uint4((uint32_t)ll[8] | ((uint32_t)ll[9] << 16), (uint32_t)ll[10] | ((uint32_t)ll[11] << 16),
                          (uint32_t)ll[12] | ((uint32_t)ll[13] << 16), (uint32_t)ll[14] | ((uint32_t)ll[15] << 16));
    *(uint4*)(Ahi + off)      = H0;
    *(uint4*)(Ahi + off + 16) = H1;
    *(uint4*)(Alo + off)      = L0;
    *(uint4*)(Alo + off + 16) = L1;
}

__global__ void __launch_bounds__(LNT, 1) lstm_kernel(
    const float* __restrict__ Wih, const float* __restrict__ Whh,
    const float* __restrict__ bih, const float* __restrict__ bhh,
    const float* __restrict__ Wfc, const float* __restrict__ bfc,
    float* __restrict__ out)
{
    extern __shared__ char smc[];
    char*  Ahi   = smc + O_AHI;
    char*  Alo   = smc + O_ALO;
    char*  Bhi   = smc + O_BHI;
    char*  Blo   = smc + O_BLO;
    float* bias2 = (float*)(smc + O_BIAS);   // [g*64+u] = (g==2)? b : 0.5b
    float* wfcs  = (float*)(smc + O_WFC);
    float* fcp   = (float*)(smc + O_FCP);

    const int tid = threadIdx.x;

    // ---- stage weights B[n][k] natural n = g*64+u; k<64: Wih, k>=64: Whh ----
    for (int i = tid; i < 256 * 128; i += LNT) {
        int n = i >> 7, k = i & 127;
        float v = (k < 64) ? Wih[n * 64 + k] : Whh[n * 64 + (k - 64)];
        unsigned short hh, ll;
        bf16split(v, hh, ll);
        uint32_t off = (uint32_t)n * ARS + (uint32_t)k * 2u;
        *(unsigned short*)(Bhi + off) = hh;
        *(unsigned short*)(Blo + off) = ll;
    }
    for (int i = tid; i < (MROW * ARS) / 4; i += LNT) {
        ((uint32_t*)Ahi)[i] = 0u;
        ((uint32_t*)Alo)[i] = 0u;
    }
    for (int i = tid; i < 256; i += LNT) {
        int g = i >> 6, u = i & 63;
        float b = bih[g * 64 + u] + bhh[g * 64 + u];
        bias2[i] = (g == 2) ? b : 0.5f * b;
    }
    if (tid < 64) wfcs[tid] = Wfc[tid];
    if (tid < MROW) fcp[tid] = 0.f;

    const int w = tid >> 5, lane = tid & 31;
    const int mp = w % 3;        // M rows 32mp..32mp+31
    const int nq = w / 3;        // 0..3: unit slice

    const uint32_t aHi = smem_u32(Ahi), aLo = smem_u32(Alo);
    const uint32_t bHi = smem_u32(Bhi), bLo = smem_u32(Blo);

    const int ai  = lane >> 3;
    const int arw = lane & 7;
    const uint32_t aRowOff = (uint32_t)(32 * mp + ((ai & 1) << 3) + arw) * ARS
                           + (uint32_t)((ai >> 1) << 4);
    const int bl  = lane & 15;
    const uint32_t bRowPart = (uint32_t)(bl & 7) * ARS + (uint32_t)(((bl >> 3) & 1) << 4);

    float cst[16];
    #pragma unroll
    for (int i = 0; i < 16; ++i) cst[i] = 0.f;
    uint32_t hpk[16];

    stage_x(Ahi, Alo, tid, blockIdx.x, 0);
    __syncthreads();

    // preload per-thread biases / fc weights: u = p*32 + nq*8 + 2(lane&3) + e
    float brs[2][2][4], wfr[2][2];
    #pragma unroll
    for (int p = 0; p < 2; ++p)
        #pragma unroll
        for (int e = 0; e < 2; ++e) {
            const int u = p * 32 + nq * 8 + 2 * (lane & 3) + e;
            #pragma unroll
            for (int g = 0; g < 4; ++g) brs[p][e][g] = bias2[g * 64 + u];
            wfr[p][e] = wfcs[u];
        }

    for (int t = 0; t < Tn; ++t) {
        const bool last = (t == Tn - 1);
        #pragma unroll
        for (int p = 0; p < 2; ++p) {
            const int u0 = p * 32 + nq * 8;
            float C[2][4][4];
            #pragma unroll
            for (int m = 0; m < 2; ++m)
                #pragma unroll
                for (int g = 0; g < 4; ++g)
                    #pragma unroll
                    for (int jj = 0; jj < 4; ++jj) C[m][g][jj] = 0.f;

            #pragma unroll
            for (int ks = 0; ks < 8; ++ks) {
                const uint32_t kb = (uint32_t)ks * 32u;
                uint32_t Ah[2][4], Al[2][4], Bh[4][2], Bl[4][2];
                #pragma unroll
                for (int m = 0; m < 2; ++m) {
                    uint32_t ro = aRowOff + (uint32_t)(16 * m) * ARS + kb;
                    LDSM4(Ah[m], aHi + ro);
                    LDSM4(Al[m], aLo + ro);
                }
                #pragma unroll
                for (int g = 0; g < 4; ++g) {
                    uint32_t ro = (uint32_t)(g * 64 + u0) * ARS + bRowPart + kb;
                    LDSM2(Bh[g], bHi + ro);
                    LDSM2(Bl[g], bLo + ro);
                }
                #pragma unroll
                for (int m = 0; m < 2; ++m)
                    #pragma unroll
                    for (int g = 0; g < 4; ++g) {
                        MMA16816(C[m][g], Ah[m], Bh[g]);
                        MMA16816(C[m][g], Al[m], Bh[g]);
                        MMA16816(C[m][g], Ah[m], Bl[g]);
                    }
            }

            // shuffle-free epilogue: gates thread-local
            #pragma unroll
            for (int m = 0; m < 2; ++m)
                #pragma unroll
                for (int rh = 0; rh < 2; ++rh)
                    #pragma unroll
                    for (int e = 0; e < 2; ++e) {
                        const int idx4 = rh * 2 + e;
                        float gi = C[m][0][idx4];
                        float gf = C[m][1][idx4];
                        float gg = C[m][2][idx4];
                        float go = C[m][3][idx4];
                        float ig = sigm2(gi, brs[p][e][0]);
                        float fg = sigm2(gf, brs[p][e][1]);
                        float g_ = tanhm(gg + brs[p][e][2]);
                        float og = sigm2(go, brs[p][e][3]);
                        const int ci = (((p * 2 + m) * 2 + rh) * 2 + e);
                        float cn = fmaf(fg, cst[ci], ig * g_);
                        cst[ci] = cn;
                        float hv = og * tanhm(cn);
                        unsigned short hh, ll;
                        bf16split(hv, hh, ll);
                        hpk[ci] = (uint32_t)hh | ((uint32_t)ll << 16);
                        if (last) {
                            const int row = 32 * mp + 16 * m + 8 * rh + (lane >> 2);
                            atomicAdd(&fcp[row], hv * wfr[p][e]);
                        }
                    }
        }
        __syncthreads();   // all warps done reading A

        // write h_t into A cols 64..127 (conflict-free 4B stores)
        #pragma unroll
        for (int p = 0; p < 2; ++p) {
            const uint32_t colb = (uint32_t)(64 + p * 32 + nq * 8 + 2 * (lane & 3)) * 2u;
            #pragma unroll
            for (int m = 0; m < 2; ++m)
                #pragma unroll
                for (int rh = 0; rh < 2; ++rh) {
                    const int ci0 = (((p * 2 + m) * 2 + rh) * 2 + 0);
                    const int ci1 = ci0 + 1;
                    const int row = 32 * mp + 16 * m + 8 * rh + (lane >> 2);
                    const uint32_t off = (uint32_t)row * ARS + colb;
                    uint32_t hi32 = (hpk[ci0] & 0xffffu) | ((hpk[ci1] & 0xffffu) << 16);
                    uint32_t lo32 = (hpk[ci0] >> 16) | ((hpk[ci1] >> 16) << 16);
                    *(uint32_t*)(Ahi + off) = hi32;
                    *(uint32_t*)(Alo + off) = lo32;
                }
        }
        if (t + 1 < Tn) stage_x(Ahi, Alo, tid, blockIdx.x, t + 1);
        __syncthreads();   // A ready for next step
    }

    if (tid < MROW) out[blockIdx.x * MROW + tid] = fcp[tid] + bfc[0];
}

// =====================================================================
extern "C" void kernel_launch(void* const* d_in, const int* in_sizes, int n_in,
                              void* d_out, int out_size)
{
    const float* x   = (const float*)d_in[0];
    // d_in[1], d_in[2] = N1, N2: structurally irrelevant (sigmoid > 0 everywhere)
    const float* W1  = (const float*)d_in[3];
    const float* b1  = (const float*)d_in[4];
    const float* W2  = (const float*)d_in[5];
    const float* b2  = (const float*)d_in[6];
    const float* Wih = (const float*)d_in[7];
    const float* Whh = (const float*)d_in[8];
    const float* bih = (const float*)d_in[9];
    const float* bhh = (const float*)d_in[10];
    const float* Wfc = (const float*)d_in[11];
    const float* bfc = (const float*)d_in[12];
    float* out = (float*)d_out;

    cudaFuncSetAttribute(gcn_kernel,  cudaFuncAttributeMaxDynamicSharedMemorySize, G_SMEM);
    cudaFuncSetAttribute(lstm_kernel, cudaFuncAttributeMaxDynamicSharedMemorySize, LSMEM);

    gcn_kernel<<<dim3(Tn, Bn), 256, G_SMEM>>>(x, W1, b1, W2, b2);
    lstm_kernel<<<LNB, LNT, LSMEM>>>(Wih, Whh, bih, bhh, Wfc, bfc, out);
}

// round 10
// speedup vs baseline: 1.9647x; 1.0532x over previous
#include <cuda_runtime.h>
#include <cuda_bf16.h>
#include <cuda_fp16.h>
#include <cstdint>

#define Bn   64
#define Nn   207
#define Tn   48
#define Fin  6
#define Hd   64
#define NSEQ (Bn * Nn)        // 13248

// scratch: GCN output / LSTM input, [seq][t][Hd]
__device__ float g_h2[(size_t)NSEQ * Tn * Hd];   // 162.8 MB

__device__ __forceinline__ float tanhm(float x) {
    float r; asm("tanh.approx.f32 %0, %1;" : "=f"(r) : "f"(x)); return r;
}
__device__ __forceinline__ float sigm2(float x, float bh) {
    return fmaf(tanhm(fmaf(x, 0.5f, bh)), 0.5f, 0.5f);
}
__device__ __forceinline__ __half2 tanh2h(__half2 v) {
    uint32_t u = *reinterpret_cast<uint32_t*>(&v), r;
    asm("tanh.approx.f16x2 %0, %1;" : "=r"(r) : "r"(u));
    return *reinterpret_cast<__half2*>(&r);
}
__device__ __forceinline__ uint32_t smem_u32(const void* p) {
    uint32_t a;
    asm("{ .reg .u64 t; cvta.to.shared.u64 t, %1; cvt.u32.u64 %0, t; }" : "=r"(a) : "l"(p));
    return a;
}

#define LDSM4(R, a) asm volatile("ldmatrix.sync.aligned.m8n8.x4.shared.b16 {%0,%1,%2,%3}, [%4];" \
    : "=r"((R)[0]), "=r"((R)[1]), "=r"((R)[2]), "=r"((R)[3]) : "r"(a))
#define LDSM2(R, a) asm volatile("ldmatrix.sync.aligned.m8n8.x2.shared.b16 {%0,%1}, [%2];" \
    : "=r"((R)[0]), "=r"((R)[1]) : "r"(a))
#define MMA16816(C, A, B) asm volatile( \
    "mma.sync.aligned.m16n8k16.row.col.f32.bf16.bf16.f32 " \
    "{%0,%1,%2,%3}, {%4,%5,%6,%7}, {%8,%9}, {%0,%1,%2,%3};" \
    : "+f"((C)[0]), "+f"((C)[1]), "+f"((C)[2]), "+f"((C)[3]) \
    : "r"((A)[0]), "r"((A)[1]), "r"((A)[2]), "r"((A)[3]), "r"((B)[0]), "r"((B)[1]))

__device__ __forceinline__ void bf16split(float v, unsigned short& h, unsigned short& l) {
    __nv_bfloat16 hb = __float2bfloat16(v);
    h = __bfloat16_as_ushort(hb);
    l = __bfloat16_as_ushort(__float2bfloat16(v - __bfloat162float(hb)));
}
__device__ __forceinline__ float bf16bits2f(uint32_t u) {
    return __uint_as_float(u << 16);
}

// =====================================================================
// Kernel 1: fused 2-layer GCN, z2 via HMMA.  grid (12, Bn), 256 thr,
// 4 timesteps per block.  A_hat[m][n] = (1 + (m==n)) / 208
// =====================================================================
#define AR2 144
#define G_AHI   25760
#define G_ALO   55712
#define G_BHI   85664
#define G_BLO   94880
#define G_SMEM  104096

__global__ void __launch_bounds__(256, 2) gcn_kernel(
    const float* __restrict__ x,  const float* __restrict__ W1,
    const float* __restrict__ b1, const float* __restrict__ W2,
    const float* __restrict__ b2)
{
    extern __shared__ char smc[];
    float* fl   = (float*)smc;
    float* W1s  = fl;               // 384
    float* W2s  = W1s + 384;        // 4096
    float* b1s  = W2s + 4096;       // 64
    float* b2s  = b1s + 64;         // 64
    float* S1   = b2s + 64;         // 64
    float* SH   = S1 + 64;          // 64
    float* xsum = SH + 64;          // 8
    float* part = xsum + 8;         // 256
    float* xs   = part + 256;       // 1248
    float* cjs  = xs + 1248;        // 64
    float* a2s  = cjs + 64;         // 64
    char*  A2h  = smc + G_AHI;
    char*  A2l  = smc + G_ALO;
    char*  B2h  = smc + G_BHI;
    char*  B2l  = smc + G_BLO;

    const int b = blockIdx.y;
    const int tid = threadIdx.x;
    const int lane = tid & 31;
    const float inv = 1.0f / 208.0f;

    for (int i = tid; i < 384;  i += 256) W1s[i] = W1[i];
    for (int i = tid; i < 4096; i += 256) W2s[i] = W2[i];
    for (int i = tid; i < 4096; i += 256) {
        int n = i >> 6, k = i & 63;
        unsigned short hh, ll;
        bf16split(W2[k * 64 + n], hh, ll);
        uint32_t off = (uint32_t)n * AR2 + (uint32_t)k * 2u;
        *(unsigned short*)(B2h + off) = hh;
        *(unsigned short*)(B2l + off) = ll;
    }
    if (tid < 64) { b1s[tid] = b1[tid]; b2s[tid] = b2[tid]; }

    for (int ti = 0; ti < 4; ++ti) {
        const int t = blockIdx.x * 4 + ti;
        {
            const float* xb = x + (size_t)b * (Nn * Tn * Fin) + t * Fin;
            for (int i = tid; i < Nn * Fin; i += 256) {
                int n = i / 6, f = i - n * 6;
                xs[i] = xb[n * (Tn * Fin) + f];
            }
        }
        __syncthreads();

        if (tid < 48) {
            int f = tid % 6, q = tid / 6;
            float s = 0.f;
            for (int n = q; n < Nn; n += 8) s += xs[n * 6 + f];
            part[tid] = s;
        }
        __syncthreads();
        if (tid < 6) {
            float s = 0.f;
            #pragma unroll
            for (int q = 0; q < 8; ++q) s += part[q * 6 + tid];
            xsum[tid] = s;
        }
        __syncthreads();
        if (tid < 64) {
            float s = 0.f;
            #pragma unroll
            for (int f = 0; f < 6; ++f) s += xsum[f] * W1s[f * 64 + tid];
            S1[tid] = s;
            cjs[tid] = fmaf(s, inv, b1s[tid]);
        }
        __syncthreads();

        if (tid < 208) {
            const int n = tid;
            float xr[6];
            #pragma unroll
            for (int f = 0; f < 6; ++f) xr[f] = (n < 207) ? xs[n * 6 + f] : 0.f;
            char* arh = A2h + (uint32_t)n * AR2;
            char* arl = A2l + (uint32_t)n * AR2;
            const int o = (lane >> 3) & 3;
            for (int s = 0; s < 32; ++s) {
                int wd = (o + s) & 31;
                int j = wd * 2;
                float v0 = xr[0] * W1s[j]       + xr[1] * W1s[64 + j]
                         + xr[2] * W1s[128 + j] + xr[3] * W1s[192 + j]
                         + xr[4] * W1s[256 + j] + xr[5] * W1s[320 + j];
                float v1 = xr[0] * W1s[j + 1]   + xr[1] * W1s[64 + j + 1]
                         + xr[2] * W1s[128 + j + 1] + xr[3] * W1s[192 + j + 1]
                         + xr[4] * W1s[256 + j + 1] + xr[5] * W1s[320 + j + 1];
                v0 = fmaxf(fmaf(v0, inv, cjs[j]), 0.f);
                v1 = fmaxf(fmaf(v1, inv, cjs[j + 1]), 0.f);
                unsigned short h0, l0, h1v, l1;
                bf16split(v0, h0, l0);
                bf16split(v1, h1v, l1);
                *(uint32_t*)(arh + j * 2) = (uint32_t)h0 | ((uint32_t)h1v << 16);
                *(uint32_t*)(arl + j * 2) = (uint32_t)l0 | ((uint32_t)l1 << 16);
            }
        }
        __syncthreads();

        {
            int j = tid & 63, q = tid >> 6;
            float s = 0.f;
            for (int n = q; n < 207; n += 4) {
                uint32_t hh = *(const unsigned short*)(A2h + (uint32_t)n * AR2 + j * 2);
                uint32_t ll = *(const unsigned short*)(A2l + (uint32_t)n * AR2 + j * 2);
                s += bf16bits2f(hh) + bf16bits2f(ll);
            }
            part[q * 64 + j] = s;
        }
        __syncthreads();
        if (tid < 64) SH[tid] = part[tid] + part[64 + tid] + part[128 + tid] + part[192 + tid];
        __syncthreads();
        if (tid < 64) {
            float s = 0.f;
            #pragma unroll 8
            for (int k = 0; k < 64; ++k) s += SH[k] * W2s[k * 64 + tid];
            a2s[tid] = fmaf(s, inv, b2s[tid]);
        }
        __syncthreads();

        {
            const int w = tid >> 5;
            const uint32_t aH = smem_u32(A2h), aL = smem_u32(A2l);
            const uint32_t bH = smem_u32(B2h), bL = smem_u32(B2l);
            const int ai = lane >> 3, arw = lane & 7;
            const int bl = lane & 15;
            const uint32_t bRowPart = (uint32_t)(bl & 7) * AR2 + (uint32_t)(((bl >> 3) & 1) << 4);

            #pragma unroll
            for (int rep = 0; rep < 2; ++rep) {
                const int mt = w + rep * 8;
                if (mt >= 13) break;
                float C[8][4];
                #pragma unroll
                for (int i = 0; i < 8; ++i)
                    #pragma unroll
                    for (int jj = 0; jj < 4; ++jj) C[i][jj] = 0.f;

                #pragma unroll
                for (int ks = 0; ks < 4; ++ks) {
                    const uint32_t kb = (uint32_t)ks * 32u;
                    uint32_t Ah[4], Al[4];
                    uint32_t ro = (uint32_t)(mt * 16 + ((ai & 1) << 3) + arw) * AR2
                                + (uint32_t)((ai >> 1) << 4) + kb;
                    LDSM4(Ah, aH + ro);
                    LDSM4(Al, aL + ro);
                    #pragma unroll
                    for (int nt = 0; nt < 8; ++nt) {
                        uint32_t rb = (uint32_t)(nt * 8) * AR2 + bRowPart + kb;
                        uint32_t Bh[2], Bl2[2];
                        LDSM2(Bh, bH + rb);
                        LDSM2(Bl2, bL + rb);
                        MMA16816(C[nt], Ah, Bh);
                        MMA16816(C[nt], Al, Bh);
                        MMA16816(C[nt], Ah, Bl2);
                    }
                }

                #pragma unroll
                for (int nt = 0; nt < 8; ++nt) {
                    const int j = nt * 8 + 2 * (lane & 3);
                    const float a0 = a2s[j], a1 = a2s[j + 1];
                    const int r0 = mt * 16 + (lane >> 2);
                    const int r1 = r0 + 8;
                    if (r0 < Nn) {
                        float2 o;
                        o.x = fmaxf(fmaf(C[nt][0], inv, a0), 0.f);
                        o.y = fmaxf(fmaf(C[nt][1], inv, a1), 0.f);
                        *(float2*)&g_h2[((size_t)(b * Nn + r0) * Tn + t) * Hd + j] = o;
                    }
                    if (r1 < Nn) {
                        float2 o;
                        o.x = fmaxf(fmaf(C[nt][2], inv, a0), 0.f);
                        o.y = fmaxf(fmaf(C[nt][3], inv, a1), 0.f);
                        *(float2*)&g_h2[((size_t)(b * Nn + r1) * Tn + t) * Hd + j] = o;
                    }
                }
            }
        }
        __syncthreads();   // protect xs/A2 for next timestep
    }
}

// =====================================================================
// Kernel 2: HMMA LSTM + FC, merged k-loop, double-buffered swizzled A,
// one sync/step, f16x2 gate tanh.  138 CTAs x 384 threads, M=96.
// A row = 256B (16 chunks of 16B), chunk swizzle: slot = ((c^(r&7))&7)|(c&8)
// =====================================================================
#define LNB  138
#define LNT  384
#define MROW 96
#define ABUF 49152            // one A buffer: hi 24576 + lo 24576
// smem byte offsets
#define O_B_HI  98304         // 256*256
#define O_B_LO  163840
#define O_BIAS  229376        // 256*4, [u][g] layout
#define O_WFC   230400        // 64*4
#define O_FCP   230656        // 96*4
#define LSMEM   231040

__device__ __forceinline__ uint32_t aswz(int row, int c16) {
    return (uint32_t)row * 256u
         + (uint32_t)((((c16) ^ (row & 7)) & 7) | ((c16) & 8)) * 16u;
}

// stage x_t (fp32 -> bf16 hi/lo) into buffer's cols 0..63.
__device__ __forceinline__ void stage_x(char* Dh, char* Dl, int tid, int blk, int t) {
    const int row = tid >> 2, cq = tid & 3;
    const float* gp = g_h2 + ((size_t)(blk * MROW + row) * Tn + t) * Hd + cq * 16;
    float f[16];
    #pragma unroll
    for (int q = 0; q < 4; ++q) {
        float4 v = ((const float4*)gp)[q];
        f[4*q] = v.x; f[4*q+1] = v.y; f[4*q+2] = v.z; f[4*q+3] = v.w;
    }
    unsigned short hh[16], ll[16];
    #pragma unroll
    for (int e = 0; e < 16; ++e) bf16split(f[e], hh[e], ll[e]);
    uint4 H0 = make_uint4((uint32_t)hh[0] | ((uint32_t)hh[1] << 16), (uint32_t)hh[2] | ((uint32_t)hh[3] << 16),
                          (uint32_t)hh[4] | ((uint32_t)hh[5] << 16), (uint32_t)hh[6] | ((uint32_t)hh[7] << 16));
    uint4 H1 = make_uint4((uint32_t)hh[8] | ((uint32_t)hh[9] << 16), (uint32_t)hh[10] | ((uint32_t)hh[11] << 16),
                          (uint32_t)hh[12] | ((uint32_t)hh[13] << 16), (uint32_t)hh[14] | ((uint32_t)hh[15] << 16));
    uint4 L0 = make_uint4((uint32_t)ll[0] | ((uint32_t)ll[1] << 16), (uint32_t)ll[2] | ((uint32_t)ll[3] << 16),
                          (uint32_t)ll[4] | ((uint32_t)ll[5] << 16), (uint32_t)ll[6] | ((uint32_t)ll[7] << 16));
    uint4 L1 = make_uint4((uint32_t)ll[8] | ((uint32_t)ll[9] << 16), (uint32_t)ll[10] | ((uint32_t)ll[11] << 16),
                          (uint32_t)ll[12] | ((uint32_t)ll[13] << 16), (uint32_t)ll[14] | ((uint32_t)ll[15] << 16));
    const uint32_t a0 = aswz(row, cq * 2);
    const uint32_t a1 = aswz(row, cq * 2 + 1);
    *(uint4*)(Dh + a0) = H0;
    *(uint4*)(Dh + a1) = H1;
    *(uint4*)(Dl + a0) = L0;
    *(uint4*)(Dl + a1) = L1;
}

__global__ void __launch_bounds__(LNT, 1) lstm_kernel(
    const float* __restrict__ Wih, const float* __restrict__ Whh,
    const float* __restrict__ bih, const float* __restrict__ bhh,
    const float* __restrict__ Wfc, const float* __restrict__ bfc,
    float* __restrict__ out)
{
    extern __shared__ char smc[];
    char*  Bhi   = smc + O_B_HI;
    char*  Blo   = smc + O_B_LO;
    float* bias2 = (float*)(smc + O_BIAS);   // [u*4+g], g==2 full else 0.5b
    float* wfcs  = (float*)(smc + O_WFC);
    float* fcp   = (float*)(smc + O_FCP);

    const int tid = threadIdx.x;

    // ---- stage weights B[n][k], n = g*64+u, swizzled rows ----
    for (int i = tid; i < 256 * 128; i += LNT) {
        int n = i >> 7, k = i & 127;
        float v = (k < 64) ? Wih[n * 64 + k] : Whh[n * 64 + (k - 64)];
        unsigned short hh, ll;
        bf16split(v, hh, ll);
        uint32_t addr = aswz(n, k >> 3) + (uint32_t)((k * 2) & 15);
        *(unsigned short*)(Bhi + addr) = hh;
        *(unsigned short*)(Blo + addr) = ll;
    }
    // zero both A buffers (h0 = 0)
    for (int i = tid; i < (2 * ABUF) / 4; i += LNT) ((uint32_t*)smc)[i] = 0u;
    for (int i = tid; i < 256; i += LNT) {
        int u = i >> 2, g = i & 3;
        float b = bih[g * 64 + u] + bhh[g * 64 + u];
        bias2[i] = (g == 2) ? b : 0.5f * b;
    }
    if (tid < 64) wfcs[tid] = Wfc[tid];
    if (tid < MROW) fcp[tid] = 0.f;
    __syncthreads();

    const int w = tid >> 5, lane = tid & 31;
    const int mp = w % 3;        // rows 32mp..+31
    const int nq = w / 3;        // unit slice

    const uint32_t sb = smem_u32(smc);
    const uint32_t bH = sb + O_B_HI, bL = sb + O_B_LO;

    const int ai  = lane >> 3;
    const int arw = lane & 7;
    const int aCsel = ai >> 1;
    const uint32_t aBase0 = (uint32_t)(32 * mp + ((ai & 1) << 3) + arw) * 256u;
    const uint32_t aBase1 = aBase0 + 16u * 256u;
    const int bl  = lane & 15;
    const int bCsel = (bl >> 3) & 1;
    const uint32_t bBase = (uint32_t)((nq * 8 + (bl & 7)) * 256);

    float cst[16];
    #pragma unroll
    for (int i = 0; i < 16; ++i) cst[i] = 0.f;

    stage_x(smc, smc + 24576, tid, blockIdx.x, 0);
    __syncthreads();

    for (int t = 0; t < Tn; ++t) {
        const int rbuf = t & 1, wbuf = rbuf ^ 1;
        const uint32_t rdHi = sb + rbuf * ABUF, rdLo = rdHi + 24576;
        const bool last = (t == Tn - 1);

        float C[2][2][4][4];
        #pragma unroll
        for (int p = 0; p < 2; ++p)
            #pragma unroll
            for (int m = 0; m < 2; ++m)
                #pragma unroll
                for (int g = 0; g < 4; ++g)
                    #pragma unroll
                    for (int jj = 0; jj < 4; ++jj) C[p][m][g][jj] = 0.f;

        #pragma unroll
        for (int ks = 0; ks < 8; ++ks) {
            const int ca = ks * 2 + aCsel;
            const uint32_t swa = (uint32_t)((((ca ^ arw) & 7) | (ca & 8)) << 4);
            const int cb = ks * 2 + bCsel;
            const uint32_t swb = (uint32_t)((((cb ^ (bl & 7)) & 7) | (cb & 8)) << 4);
            uint32_t Ah[2][4], Al[2][4];
            {
                const uint32_t a0 = aBase0 + swa, a1 = aBase1 + swa;
                LDSM4(Ah[0], rdHi + a0);
                LDSM4(Al[0], rdLo + a0);
                LDSM4(Ah[1], rdHi + a1);
                LDSM4(Al[1], rdLo + a1);
            }
            #pragma unroll
            for (int p = 0; p < 2; ++p)
                #pragma unroll
                for (int g = 0; g < 4; ++g) {
                    const uint32_t bo = bBase + (uint32_t)(g * 16384 + p * 8192) + swb;
                    uint32_t Bh[2], Bl2[2];
                    LDSM2(Bh, bH + bo);
                    MMA16816(C[p][0][g], Ah[0], Bh);
                    MMA16816(C[p][1][g], Ah[1], Bh);
                    MMA16816(C[p][0][g], Al[0], Bh);
                    MMA16816(C[p][1][g], Al[1], Bh);
                    LDSM2(Bl2, bL + bo);
                    MMA16816(C[p][0][g], Ah[0], Bl2);
                    MMA16816(C[p][1][g], Ah[1], Bl2);
                }
        }

        // epilogue: write h_t straight into the OTHER buffer (no readers there)
        {
            char* WH = smc + wbuf * ABUF;
            char* WL = WH + 24576;
            #pragma unroll
            for (int p = 0; p < 2; ++p) {
                const int c16 = 8 + p * 4 + nq;
                #pragma unroll
                for (int m = 0; m < 2; ++m)
                    #pragma unroll
                    for (int rh = 0; rh < 2; ++rh) {
                        const int row = 32 * mp + 16 * m + 8 * rh + (lane >> 2);
                        const uint32_t off = (uint32_t)row * 256u
                            + (uint32_t)((((c16 ^ (row & 7)) & 7) | 8) << 4)
                            + (uint32_t)(4 * (lane & 3));
                        uint32_t hiw = 0u, low = 0u;
                        #pragma unroll
                        for (int e = 0; e < 2; ++e) {
                            const int u = p * 32 + nq * 8 + 2 * (lane & 3) + e;
                            const float4 bb = *(const float4*)(bias2 + 4 * u);
                            const int idx4 = rh * 2 + e;
                            const float gi = C[p][m][0][idx4];
                            const float gf = C[p][m][1][idx4];
                            const float gg = C[p][m][2][idx4];
                            const float go = C[p][m][3][idx4];
                            __half2 pk1 = __floats2half2_rn(fmaf(gi, 0.5f, bb.x),
                                                            fmaf(gf, 0.5f, bb.y));
                            __half2 pk2 = __floats2half2_rn(gg + bb.z,
                                                            fmaf(go, 0.5f, bb.w));
                            float2 t1 = __half22float2(tanh2h(pk1));
                            float2 t2 = __half22float2(tanh2h(pk2));
                            const float ig = fmaf(t1.x, 0.5f, 0.5f);
                            const float fg = fmaf(t1.y, 0.5f, 0.5f);
                            const float g_ = t2.x;
                            const float og = fmaf(t2.y, 0.5f, 0.5f);
                            const int ci = ((p * 2 + m) * 2 + rh) * 2 + e;
                            const float cn = fmaf(fg, cst[ci], ig * g_);
                            cst[ci] = cn;
                            const float hv = og * tanhm(cn);
                            unsigned short hh, ll;
                            bf16split(hv, hh, ll);
                            hiw |= ((uint32_t)hh) << (16 * e);
                            low |= ((uint32_t)ll) << (16 * e);
                            if (last) atomicAdd(&fcp[row], hv * wfcs[u]);
                        }
                        *(uint32_t*)(WH + off) = hiw;
                        *(uint32_t*)(WL + off) = low;
                    }
            }
        }

        if (t + 1 < Tn)
            stage_x(smc + wbuf * ABUF, smc + wbuf * ABUF + 24576, tid, blockIdx.x, t + 1);
        __syncthreads();   // single barrier per step
    }

    if (tid < MROW) out[blockIdx.x * MROW + tid] = fcp[tid] + bfc[0];
}

// =====================================================================
extern "C" void kernel_launch(void* const* d_in, const int* in_sizes, int n_in,
                              void* d_out, int out_size)
{
    const float* x   = (const float*)d_in[0];
    // d_in[1], d_in[2] = N1, N2: structurally irrelevant (sigmoid > 0 everywhere)
    const float* W1  = (const float*)d_in[3];
    const float* b1  = (const float*)d_in[4];
    const float* W2  = (const float*)d_in[5];
    const float* b2  = (const float*)d_in[6];
    const float* Wih = (const float*)d_in[7];
    const float* Whh = (const float*)d_in[8];
    const float* bih = (const float*)d_in[9];
    const float* bhh = (const float*)d_in[10];
    const float* Wfc = (const float*)d_in[11];
    const float* bfc = (const float*)d_in[12];
    float* out = (float*)d_out;

    cudaFuncSetAttribute(gcn_kernel,  cudaFuncAttributeMaxDynamicSharedMemorySize, G_SMEM);
    cudaFuncSetAttribute(lstm_kernel, cudaFuncAttributeMaxDynamicSharedMemorySize, LSMEM);

    gcn_kernel<<<dim3(Tn / 4, Bn), 256, G_SMEM>>>(x, W1, b1, W2, b2);
    lstm_kernel<<<LNB, LNT, LSMEM>>>(Wih, Whh, bih, bhh, Wfc, bfc, out);
}